// round 5
// baseline (speedup 1.0000x reference)
#include <cuda_runtime.h>
#include <math.h>
#include <stdint.h>

#define S_TOK 8192
#define DM    1024
#define FFDIM 4096
#define NE    8
#define CAP   1280

#define BM 128
#define BN 128
#define BK 32
#define NSTG 4
#define RS 36                               // BK + 4 floats
#define A_FLOATS (BM * RS)                  // 4608
#define STG_FLOATS (2 * A_FLOATS)           // 9216
#define STG_BYTES  (STG_FLOATS * 4)         // 36864
#define SMEM_BYTES (NSTG * STG_BYTES)       // 147456

// ---------------- scratch (device globals; no allocation allowed) ----------------
__device__ int   g_topk_i[S_TOK * 2];
__device__ float g_topk_w[S_TOK * 2];
__device__ int   g_slot[S_TOK * 2];
__device__ int   g_idx[NE * CAP];
__device__ int   g_cnt[NE];
__device__ float g_xin[(size_t)NE * CAP * DM];      // gathered + tf32-rounded x (zero padded)
__device__ float g_w1t[(size_t)NE * FFDIM * DM];    // w1 -> [e][FF][DM] K-major, rounded
__device__ float g_w2t[(size_t)NE * DM * FFDIM];    // w2 -> [e][DM][FF] K-major, rounded
__device__ float g_h  [(size_t)NE * CAP * FFDIM];   // hidden (rounded in epilogue)
__device__ float g_oute[(size_t)NE * CAP * DM];     // expert outputs

__device__ __forceinline__ float to_tf32(float x) {
    unsigned u;
    asm("cvt.rna.tf32.f32 %0, %1;" : "=r"(u) : "f"(x));
    return __uint_as_float(u);
}

__device__ __forceinline__ void mma_tf32(float* d, const unsigned* a, const unsigned* b) {
    asm volatile(
        "mma.sync.aligned.m16n8k8.row.col.f32.tf32.tf32.f32 "
        "{%0,%1,%2,%3}, {%4,%5,%6,%7}, {%8,%9}, {%0,%1,%2,%3};\n"
        : "+f"(d[0]), "+f"(d[1]), "+f"(d[2]), "+f"(d[3])
        : "r"(a[0]), "r"(a[1]), "r"(a[2]), "r"(a[3]), "r"(b[0]), "r"(b[1]));
}

__device__ __forceinline__ void cp16(unsigned dst, const void* src) {
    asm volatile("cp.async.ca.shared.global [%0], [%1], 16;\n" :: "r"(dst), "l"(src));
}
__device__ __forceinline__ void cp_commit() { asm volatile("cp.async.commit_group;\n"); }
__device__ __forceinline__ void cp_wait2()  { asm volatile("cp.async.wait_group 2;\n"); }

// ---------------- gating ----------------
__global__ __launch_bounds__(256) void gate_kernel(const float* __restrict__ x,
                                                   const float* __restrict__ gw,
                                                   const float* __restrict__ gb) {
    __shared__ float sgw[DM * 9];
    int tid = threadIdx.x;
    for (int i = tid; i < DM * NE; i += 256) sgw[(i >> 3) * 9 + (i & 7)] = gw[i];
    __syncthreads();

    int warp = tid >> 5, lane = tid & 31;
    int t = blockIdx.x * 8 + warp;
    const float* xr = x + (size_t)t * DM;
    float acc[NE];
#pragma unroll
    for (int e = 0; e < NE; e++) acc[e] = 0.f;
    for (int d = lane; d < DM; d += 32) {
        float xv = xr[d];
        const float* g = &sgw[d * 9];
#pragma unroll
        for (int e = 0; e < NE; e++) acc[e] += xv * g[e];
    }
#pragma unroll
    for (int e = 0; e < NE; e++) {
#pragma unroll
        for (int off = 16; off; off >>= 1)
            acc[e] += __shfl_xor_sync(0xffffffffu, acc[e], off);
    }
    if (lane == 0) {
        float l[NE];
#pragma unroll
        for (int e = 0; e < NE; e++) l[e] = acc[e] + gb[e];
        int i0 = 0;
#pragma unroll
        for (int e = 1; e < NE; e++) if (l[e] > l[i0]) i0 = e;
        int i1 = (i0 == 0) ? 1 : 0;
#pragma unroll
        for (int e = 0; e < NE; e++) if (e != i0 && l[e] > l[i1]) i1 = e;
        float p1 = expf(l[i1] - l[i0]);
        float w0 = 1.f / (1.f + p1);
        g_topk_i[2 * t] = i0; g_topk_i[2 * t + 1] = i1;
        g_topk_w[2 * t] = w0; g_topk_w[2 * t + 1] = 1.f - w0;
    }
}

// ---------------- routing ----------------
__global__ __launch_bounds__(256) void route_kernel() {
    __shared__ int wsum[8];
    __shared__ int run[NE];
    int tid = threadIdx.x, lane = tid & 31, warp = tid >> 5;
    if (tid < NE) run[tid] = 0;
    __syncthreads();

    for (int base = 0; base < S_TOK; base += 256) {
        int t = base + tid;
        int i0 = g_topk_i[2 * t], i1 = g_topk_i[2 * t + 1];
        int rank0 = 0, rank1 = 0;
        for (int e = 0; e < NE; e++) {
            int v = (i0 == e || i1 == e) ? 1 : 0;
#pragma unroll
            for (int off = 1; off < 32; off <<= 1) {
                int u = __shfl_up_sync(0xffffffffu, v, off);
                if (lane >= off) v += u;
            }
            if (lane == 31) wsum[warp] = v;
            __syncthreads();
            int woff = 0, total = 0;
#pragma unroll
            for (int w = 0; w < 8; w++) { int s = wsum[w]; total += s; if (w < warp) woff += s; }
            int rank = run[e] + woff + v;
            if (i0 == e) rank0 = rank;
            if (i1 == e) rank1 = rank;
            __syncthreads();
            if (tid == 0) run[e] += total;
        }
        int s0 = (rank0 <= CAP) ? rank0 - 1 : -1;
        int s1 = (rank1 <= CAP) ? rank1 - 1 : -1;
        g_slot[2 * t] = s0; g_slot[2 * t + 1] = s1;
        if (s0 >= 0) g_idx[i0 * CAP + s0] = t;
        if (s1 >= 0) g_idx[i1 * CAP + s1] = t;
    }
    __syncthreads();
    if (tid < NE) g_cnt[tid] = min(run[tid], CAP);
}

// ---------------- gather x -> g_xin (rounded, zero-padded) ----------------
__global__ __launch_bounds__(256) void xin_kernel(const float* __restrict__ x) {
    int c = blockIdx.x, e = blockIdx.y;
    int tok = (c < g_cnt[e]) ? g_idx[e * CAP + c] : -1;
    float* dst = g_xin + ((size_t)e * CAP + c) * DM + threadIdx.x * 4;
    if (tok < 0) {
        *reinterpret_cast<float4*>(dst) = make_float4(0.f, 0.f, 0.f, 0.f);
    } else {
        float4 v = *reinterpret_cast<const float4*>(x + (size_t)tok * DM + threadIdx.x * 4);
        v.x = to_tf32(v.x); v.y = to_tf32(v.y); v.z = to_tf32(v.z); v.w = to_tf32(v.w);
        *reinterpret_cast<float4*>(dst) = v;
    }
}

// ---------------- transpose + round weights: src[e][R][C] -> dst[e][C][R] ----------------
template<bool W1>
__global__ __launch_bounds__(256) void wtr_kernel(const float* __restrict__ src) {
    constexpr int R = W1 ? DM : FFDIM;
    constexpr int C = W1 ? FFDIM : DM;
    float* dst = W1 ? g_w1t : g_w2t;
    __shared__ float tile[32][33];
    int e = blockIdx.z;
    int c0 = blockIdx.x * 32, r0 = blockIdx.y * 32;
    const float* s = src + (size_t)e * R * C;
    float* d = dst + (size_t)e * R * C;
    int tx = threadIdx.x & 31, ty = threadIdx.x >> 5;   // 32x8
#pragma unroll
    for (int i = 0; i < 32; i += 8)
        tile[ty + i][tx] = s[(size_t)(r0 + ty + i) * C + c0 + tx];
    __syncthreads();
#pragma unroll
    for (int i = 0; i < 32; i += 8)
        d[(size_t)(c0 + ty + i) * R + r0 + tx] = to_tf32(tile[tx][ty + i]);
}

// ---------------- expert GEMM: tf32 mma.sync, multistage pipelined ----------------
// 512 threads, 16 warps in 4x4 grid, warp tile 32x32, BK=32 (4 k-groups/stage),
// fragment double-buffering, pre-rounded K-major operands, float2 (LDS.64) frags.
// k-slot permutation: logical slots (tig, tig+4) <- physical cols (2*tig, 2*tig+1),
// applied identically to A and B (sum over k is permutation-invariant).
template<bool PHASE1>
__global__ __launch_bounds__(512, 1)
void gemm_kernel(const float* __restrict__ biasGlob) {
    constexpr int KDIM = PHASE1 ? DM : FFDIM;
    constexpr int NDIM = PHASE1 ? FFDIM : DM;
    constexpr int NIT = KDIM / BK;

    extern __shared__ float smem[];

    const int e = blockIdx.z;
    const int rowBase = blockIdx.y * BM;
    const int nBase = blockIdx.x * BN;
    const int tid = threadIdx.x;

    const float* Ab = (PHASE1 ? g_xin : g_h) + ((size_t)e * CAP + rowBase) * KDIM;
    const float* Bb = (PHASE1 ? g_w1t : g_w2t) + ((size_t)e * NDIM + nBase) * KDIM;
    const float* bias = biasGlob + e * NDIM;
    float* Out = (PHASE1 ? g_h : g_oute) + (size_t)e * CAP * NDIM;

    const unsigned smem_base = (unsigned)__cvta_generic_to_shared(smem);

    // cp.async: 1024 chunks of 16B per operand per stage; 512 threads -> 2 chunks each
    const int ldRow = tid >> 2;        // 0..127
    const int ldC4a = tid & 3;         // chunks 0..3 and 4..7

    auto load_stage = [&](int slot, int kk) {
        unsigned aB = smem_base + slot * STG_BYTES;
        unsigned bB = aB + A_FLOATS * 4;
#pragma unroll
        for (int i = 0; i < 2; i++) {
            int c4 = ldC4a + i * 4;
            cp16(aB + (ldRow * RS + c4 * 4) * 4, Ab + (size_t)ldRow * KDIM + kk + c4 * 4);
            cp16(bB + (ldRow * RS + c4 * 4) * 4, Bb + (size_t)ldRow * KDIM + kk + c4 * 4);
        }
    };

    float acc[2][4][4];
#pragma unroll
    for (int mt = 0; mt < 2; mt++)
#pragma unroll
        for (int nt = 0; nt < 4; nt++)
#pragma unroll
            for (int i = 0; i < 4; i++) acc[mt][nt][i] = 0.f;

    const int warp = tid >> 5, lane = tid & 31;
    const int wm = warp >> 2, wn = warp & 3;       // 4x4 warp grid; warp tile 32x32
    const int gid = lane >> 2, tig = lane & 3;
    const int t2 = 2 * tig;

    unsigned fa[2][2][4], fb[2][4][2];             // [buf][mt][.] / [buf][nt][.]

    const int ar0 = wm * 32 + gid;                 // A rows: ar0+mt*16 (+8)
    const int bc0 = wn * 32 + gid;                 // B cols: bc0+nt*8

    auto load_frag = [&](int buf, const float* SA, const float* SB, int kf) {
#pragma unroll
        for (int mt = 0; mt < 2; mt++) {
            int r = ar0 + mt * 16;
            float2 lo = *reinterpret_cast<const float2*>(&SA[r * RS + kf + t2]);
            float2 hi = *reinterpret_cast<const float2*>(&SA[(r + 8) * RS + kf + t2]);
            fa[buf][mt][0] = __float_as_uint(lo.x);
            fa[buf][mt][1] = __float_as_uint(hi.x);
            fa[buf][mt][2] = __float_as_uint(lo.y);
            fa[buf][mt][3] = __float_as_uint(hi.y);
        }
#pragma unroll
        for (int nt = 0; nt < 4; nt++) {
            float2 bf = *reinterpret_cast<const float2*>(&SB[(bc0 + nt * 8) * RS + kf + t2]);
            fb[buf][nt][0] = __float_as_uint(bf.x);
            fb[buf][nt][1] = __float_as_uint(bf.y);
        }
    };
    auto do_mma = [&](int buf) {
#pragma unroll
        for (int mt = 0; mt < 2; mt++)
#pragma unroll
            for (int nt = 0; nt < 4; nt++)
                mma_tf32(acc[mt][nt], fa[buf][mt], fb[buf][nt]);
    };

    // prologue: fill NSTG-1 stages, arm stage 0, preload first fragment
#pragma unroll
    for (int s = 0; s < NSTG - 1; s++) { load_stage(s, s * BK); cp_commit(); }
    cp_wait2();
    __syncthreads();
    load_frag(0, smem, smem + A_FLOATS, 0);

    for (int k = 0; k < NIT; k++) {
        int nk = k + NSTG - 1;
        if (nk < NIT) load_stage(nk & (NSTG - 1), nk * BK);
        cp_commit();

        const float* SA = smem + (k & (NSTG - 1)) * STG_FLOATS;
        const float* SB = SA + A_FLOATS;

        load_frag(1, SA, SB, 8);
        do_mma(0);
        load_frag(0, SA, SB, 16);
        do_mma(1);
        load_frag(1, SA, SB, 24);
        do_mma(0);

        cp_wait2();
        __syncthreads();
        if (k + 1 < NIT) {
            const float* SA2 = smem + ((k + 1) & (NSTG - 1)) * STG_FLOATS;
            load_frag(0, SA2, SA2 + A_FLOATS, 0);
        }
        do_mma(1);
    }

    // epilogue: + bias (, relu + round), store
#pragma unroll
    for (int mt = 0; mt < 2; mt++) {
        int r0 = rowBase + ar0 + mt * 16;
#pragma unroll
        for (int nt = 0; nt < 4; nt++) {
            int c = nBase + wn * 32 + nt * 8 + t2;
            float bv0 = bias[c], bv1 = bias[c + 1];
            float v00 = acc[mt][nt][0] + bv0;
            float v01 = acc[mt][nt][1] + bv1;
            float v10 = acc[mt][nt][2] + bv0;
            float v11 = acc[mt][nt][3] + bv1;
            if (PHASE1) {
                v00 = to_tf32(fmaxf(v00, 0.f)); v01 = to_tf32(fmaxf(v01, 0.f));
                v10 = to_tf32(fmaxf(v10, 0.f)); v11 = to_tf32(fmaxf(v11, 0.f));
            }
            *reinterpret_cast<float2*>(Out + (size_t)r0 * NDIM + c) = make_float2(v00, v01);
            *reinterpret_cast<float2*>(Out + (size_t)(r0 + 8) * NDIM + c) = make_float2(v10, v11);
        }
    }
}

// ---------------- combine ----------------
__global__ __launch_bounds__(256) void combine_kernel(float* __restrict__ out) {
    int t = blockIdx.x;
    int i0 = g_topk_i[2 * t], i1 = g_topk_i[2 * t + 1];
    int s0 = g_slot[2 * t], s1 = g_slot[2 * t + 1];
    float w0 = g_topk_w[2 * t], w1v = g_topk_w[2 * t + 1];
    int d = threadIdx.x * 4;
    float4 a = make_float4(0.f, 0.f, 0.f, 0.f);
    if (s0 >= 0) {
        float4 v = *reinterpret_cast<const float4*>(g_oute + ((size_t)i0 * CAP + s0) * DM + d);
        a.x += w0 * v.x; a.y += w0 * v.y; a.z += w0 * v.z; a.w += w0 * v.w;
    }
    if (s1 >= 0) {
        float4 v = *reinterpret_cast<const float4*>(g_oute + ((size_t)i1 * CAP + s1) * DM + d);
        a.x += w1v * v.x; a.y += w1v * v.y; a.z += w1v * v.z; a.w += w1v * v.w;
    }
    *reinterpret_cast<float4*>(out + (size_t)t * DM + d) = a;
}

// ---------------- launch ----------------
extern "C" void kernel_launch(void* const* d_in, const int* in_sizes, int n_in,
                              void* d_out, int out_size) {
    (void)in_sizes; (void)n_in; (void)out_size;
    const float* x      = (const float*)d_in[0];
    const float* gate_w = (const float*)d_in[1];
    const float* gate_b = (const float*)d_in[2];
    const float* w1     = (const float*)d_in[3];
    const float* b1     = (const float*)d_in[4];
    const float* w2     = (const float*)d_in[5];
    const float* b2     = (const float*)d_in[6];
    float* out = (float*)d_out;

    static bool attr_done = false;
    if (!attr_done) {
        cudaFuncSetAttribute(gemm_kernel<true>,
                             cudaFuncAttributeMaxDynamicSharedMemorySize, SMEM_BYTES);
        cudaFuncSetAttribute(gemm_kernel<false>,
                             cudaFuncAttributeMaxDynamicSharedMemorySize, SMEM_BYTES);
        attr_done = true;
    }

    gate_kernel<<<S_TOK / 8, 256>>>(x, gate_w, gate_b);
    route_kernel<<<1, 256>>>();
    xin_kernel<<<dim3(CAP, NE), 256>>>(x);
    wtr_kernel<true ><<<dim3(FFDIM / 32, DM / 32, NE), 256>>>(w1);
    wtr_kernel<false><<<dim3(DM / 32, FFDIM / 32, NE), 256>>>(w2);
    gemm_kernel<true >
        <<<dim3(FFDIM / BN, CAP / BM, NE), 512, SMEM_BYTES>>>(b1);
    gemm_kernel<false>
        <<<dim3(DM / BN,    CAP / BM, NE), 512, SMEM_BYTES>>>(b2);
    combine_kernel<<<S_TOK, 256>>>(out);
}

// round 6
// speedup vs baseline: 1.4146x; 1.4146x over previous
#include <cuda_runtime.h>
#include <math.h>

#define S_TOK 8192
#define DM    1024
#define FFDIM 4096
#define NE    8
#define CAP   1280

#define BM 128
#define BN 128
#define BK 16
#define STAGES 4
#define ASTR 20    // BK + 4 floats
#define BSTR 136   // BN + 8 floats

#define A_STAGE_BYTES (BM * ASTR * 4)          // 10240
#define B_STAGE_BYTES (BK * BSTR * 4)          // 8704
#define STAGE_BYTES   (A_STAGE_BYTES + B_STAGE_BYTES)
#define SMEM_BYTES    (STAGES * STAGE_BYTES)   // 75776

// ---------------- scratch (device globals; no allocation allowed) ----------------
__device__ int   g_topk_i[S_TOK * 2];
__device__ float g_topk_w[S_TOK * 2];
__device__ int   g_slot[S_TOK * 2];
__device__ int   g_idx[NE * CAP];
__device__ int   g_cnt[NE];
__device__ float g_xr [(size_t)S_TOK * DM];         // tf32-rounded x (token order)
__device__ float g_w1r[(size_t)NE * DM * FFDIM];    // tf32-rounded w1 (same layout)
__device__ float g_w2r[(size_t)NE * FFDIM * DM];    // tf32-rounded w2 (same layout)
__device__ float g_h  [(size_t)NE * CAP * FFDIM];   // hidden (rounded in epilogue)
__device__ float g_oute[(size_t)NE * CAP * DM];     // expert outputs

__device__ __forceinline__ float to_tf32(float x) {
    unsigned u;
    asm("cvt.rna.tf32.f32 %0, %1;" : "=r"(u) : "f"(x));
    return __uint_as_float(u);
}

__device__ __forceinline__ void mma_tf32(float* d, const unsigned* a, const unsigned* b) {
    asm volatile(
        "mma.sync.aligned.m16n8k8.row.col.f32.tf32.tf32.f32 "
        "{%0,%1,%2,%3}, {%4,%5,%6,%7}, {%8,%9}, {%0,%1,%2,%3};\n"
        : "+f"(d[0]), "+f"(d[1]), "+f"(d[2]), "+f"(d[3])
        : "r"(a[0]), "r"(a[1]), "r"(a[2]), "r"(a[3]), "r"(b[0]), "r"(b[1]));
}

__device__ __forceinline__ void cp_async16(unsigned smem_addr, const void* gptr, int src_bytes) {
    asm volatile("cp.async.ca.shared.global [%0], [%1], 16, %2;\n"
                 :: "r"(smem_addr), "l"(gptr), "r"(src_bytes));
}
__device__ __forceinline__ void cp_commit() {
    asm volatile("cp.async.commit_group;\n");
}
__device__ __forceinline__ void cp_wait2() {
    asm volatile("cp.async.wait_group 2;\n");
}

// ---------------- elementwise tf32 rounding copy (float4, grid-stride) ----------------
__global__ __launch_bounds__(256) void round_kernel(const float4* __restrict__ src,
                                                    float4* __restrict__ dst,
                                                    int n4) {
    int i = blockIdx.x * 256 + threadIdx.x;
    int stride = gridDim.x * 256;
    for (; i < n4; i += stride) {
        float4 v = src[i];
        v.x = to_tf32(v.x); v.y = to_tf32(v.y); v.z = to_tf32(v.z); v.w = to_tf32(v.w);
        dst[i] = v;
    }
}

// ---------------- gating: logits -> top2 -> normalized weights ----------------
__global__ __launch_bounds__(256) void gate_kernel(const float* __restrict__ x,
                                                   const float* __restrict__ gw,
                                                   const float* __restrict__ gb) {
    __shared__ float sgw[DM * 9];
    int tid = threadIdx.x;
    for (int i = tid; i < DM * NE; i += 256) sgw[(i >> 3) * 9 + (i & 7)] = gw[i];
    __syncthreads();

    int warp = tid >> 5, lane = tid & 31;
    int t = blockIdx.x * 8 + warp;
    const float* xr = x + (size_t)t * DM;
    float acc[NE];
#pragma unroll
    for (int e = 0; e < NE; e++) acc[e] = 0.f;
    for (int d = lane; d < DM; d += 32) {
        float xv = xr[d];
        const float* g = &sgw[d * 9];
#pragma unroll
        for (int e = 0; e < NE; e++) acc[e] += xv * g[e];
    }
#pragma unroll
    for (int e = 0; e < NE; e++) {
#pragma unroll
        for (int off = 16; off; off >>= 1)
            acc[e] += __shfl_xor_sync(0xffffffffu, acc[e], off);
    }
    if (lane == 0) {
        float l[NE];
#pragma unroll
        for (int e = 0; e < NE; e++) l[e] = acc[e] + gb[e];
        int i0 = 0;
#pragma unroll
        for (int e = 1; e < NE; e++) if (l[e] > l[i0]) i0 = e;
        int i1 = (i0 == 0) ? 1 : 0;
#pragma unroll
        for (int e = 0; e < NE; e++) if (e != i0 && l[e] > l[i1]) i1 = e;
        float p1 = expf(l[i1] - l[i0]);
        float w0 = 1.f / (1.f + p1);
        g_topk_i[2 * t] = i0; g_topk_i[2 * t + 1] = i1;
        g_topk_w[2 * t] = w0; g_topk_w[2 * t + 1] = 1.f - w0;
    }
}

// ---------------- routing: order-preserving capacity assignment ----------------
__global__ __launch_bounds__(256) void route_kernel() {
    __shared__ int wsum[8];
    __shared__ int run[NE];
    int tid = threadIdx.x, lane = tid & 31, warp = tid >> 5;
    if (tid < NE) run[tid] = 0;
    __syncthreads();

    for (int base = 0; base < S_TOK; base += 256) {
        int t = base + tid;
        int i0 = g_topk_i[2 * t], i1 = g_topk_i[2 * t + 1];
        int rank0 = 0, rank1 = 0;
        for (int e = 0; e < NE; e++) {
            int v = (i0 == e || i1 == e) ? 1 : 0;
#pragma unroll
            for (int off = 1; off < 32; off <<= 1) {
                int u = __shfl_up_sync(0xffffffffu, v, off);
                if (lane >= off) v += u;
            }
            if (lane == 31) wsum[warp] = v;
            __syncthreads();
            int woff = 0, total = 0;
#pragma unroll
            for (int w = 0; w < 8; w++) { int s = wsum[w]; total += s; if (w < warp) woff += s; }
            int rank = run[e] + woff + v;
            if (i0 == e) rank0 = rank;
            if (i1 == e) rank1 = rank;
            __syncthreads();
            if (tid == 0) run[e] += total;
        }
        int s0 = (rank0 <= CAP) ? rank0 - 1 : -1;
        int s1 = (rank1 <= CAP) ? rank1 - 1 : -1;
        g_slot[2 * t] = s0; g_slot[2 * t + 1] = s1;
        if (s0 >= 0) g_idx[i0 * CAP + s0] = t;
        if (s1 >= 0) g_idx[i1 * CAP + s1] = t;
    }
    __syncthreads();
    if (tid < NE) g_cnt[tid] = min(run[tid], CAP);
}

// ---------------- expert GEMM: tf32 mma.sync + 4-stage cp.async, pre-rounded operands ----------------
template<bool GATHER, bool RELU, int KDIM, int NDIM>
__global__ __launch_bounds__(256, 2)
void gemm_kernel(const float* __restrict__ Aglob,
                 const float* __restrict__ Wglob,
                 const float* __restrict__ biasGlob) {
    extern __shared__ char smem[];
    __shared__ int sTok[BM];

    const int e = blockIdx.z;
    const int rowBase = blockIdx.y * BM;
    const int nBase = blockIdx.x * BN;
    const int tid = threadIdx.x;

    const float* Abase = GATHER ? Aglob : (g_h + (size_t)e * CAP * KDIM);
    const float* W = Wglob + (size_t)e * KDIM * NDIM;
    const float* bias = biasGlob + e * NDIM;
    float* Out = (RELU ? g_h : g_oute) + (size_t)e * CAP * NDIM;

    if (tid < BM) {
        int r = rowBase + tid;
        sTok[tid] = GATHER ? ((r < g_cnt[e]) ? g_idx[e * CAP + r] : -1) : r;
    }
    __syncthreads();

    const unsigned smem_base = (unsigned)__cvta_generic_to_shared(smem);

    const int aRow0 = tid >> 2, aC4 = (tid & 3);
    const int bRow0 = tid >> 5, bC4 = (tid & 31);

    auto load_stage = [&](int s, int kk) {
        unsigned aBase = smem_base + s * STAGE_BYTES;
        unsigned bBase = aBase + A_STAGE_BYTES;
#pragma unroll
        for (int i = 0; i < 2; i++) {
            int row = aRow0 + i * 64;
            int tok = sTok[row];
            unsigned dst = aBase + (row * ASTR + aC4 * 4) * 4;
            const float* src = Abase + (size_t)((tok < 0) ? 0 : tok) * KDIM + kk + aC4 * 4;
            cp_async16(dst, src, (tok >= 0) ? 16 : 0);
        }
#pragma unroll
        for (int i = 0; i < 2; i++) {
            int row = bRow0 + i * 8;
            unsigned dst = bBase + (row * BSTR + bC4 * 4) * 4;
            const float* src = W + (size_t)(kk + row) * NDIM + nBase + bC4 * 4;
            cp_async16(dst, src, 16);
        }
    };

    float acc[4][4][4];
#pragma unroll
    for (int mt = 0; mt < 4; mt++)
#pragma unroll
        for (int nt = 0; nt < 4; nt++)
#pragma unroll
            for (int i = 0; i < 4; i++) acc[mt][nt][i] = 0.f;

    const int warp = tid >> 5, lane = tid & 31;
    const int wm = warp >> 2, wn = warp & 3;       // 2x4 warp grid; warp tile 64x32
    const int gid = lane >> 2, tig = lane & 3;

    const int NIT = KDIM / BK;

#pragma unroll
    for (int s = 0; s < STAGES - 1; s++) {
        load_stage(s, s * BK);
        cp_commit();
    }

    for (int k = 0; k < NIT; k++) {
        cp_wait2();
        __syncthreads();

        int nk = k + STAGES - 1;
        if (nk < NIT) load_stage(nk & (STAGES - 1), nk * BK);
        cp_commit();

        const int s = k & (STAGES - 1);
        const float* As = (const float*)(smem + s * STAGE_BYTES);
        const float* Bs = (const float*)(smem + s * STAGE_BYTES + A_STAGE_BYTES);

#pragma unroll
        for (int kf = 0; kf < BK; kf += 8) {
            unsigned a[4][4], b[4][2];
#pragma unroll
            for (int mt = 0; mt < 4; mt++) {
                int r = wm * 64 + mt * 16 + gid;
                a[mt][0] = __float_as_uint(As[r * ASTR + kf + tig]);
                a[mt][1] = __float_as_uint(As[(r + 8) * ASTR + kf + tig]);
                a[mt][2] = __float_as_uint(As[r * ASTR + kf + tig + 4]);
                a[mt][3] = __float_as_uint(As[(r + 8) * ASTR + kf + tig + 4]);
            }
#pragma unroll
            for (int nt = 0; nt < 4; nt++) {
                int c = wn * 32 + nt * 8 + gid;
                b[nt][0] = __float_as_uint(Bs[(kf + tig) * BSTR + c]);
                b[nt][1] = __float_as_uint(Bs[(kf + tig + 4) * BSTR + c]);
            }
#pragma unroll
            for (int mt = 0; mt < 4; mt++)
#pragma unroll
                for (int nt = 0; nt < 4; nt++)
                    mma_tf32(acc[mt][nt], a[mt], b[nt]);
        }
    }

    // epilogue: + bias (, relu + round), store
#pragma unroll
    for (int mt = 0; mt < 4; mt++) {
        int r0 = rowBase + wm * 64 + mt * 16 + gid;
#pragma unroll
        for (int nt = 0; nt < 4; nt++) {
            int c = nBase + wn * 32 + nt * 8 + 2 * tig;
            float bv0 = bias[c], bv1 = bias[c + 1];
            float v00 = acc[mt][nt][0] + bv0;
            float v01 = acc[mt][nt][1] + bv1;
            float v10 = acc[mt][nt][2] + bv0;
            float v11 = acc[mt][nt][3] + bv1;
            if (RELU) {
                v00 = to_tf32(fmaxf(v00, 0.f)); v01 = to_tf32(fmaxf(v01, 0.f));
                v10 = to_tf32(fmaxf(v10, 0.f)); v11 = to_tf32(fmaxf(v11, 0.f));
            }
            *reinterpret_cast<float2*>(Out + (size_t)r0 * NDIM + c) = make_float2(v00, v01);
            *reinterpret_cast<float2*>(Out + (size_t)(r0 + 8) * NDIM + c) = make_float2(v10, v11);
        }
    }
}

// ---------------- combine ----------------
__global__ __launch_bounds__(256) void combine_kernel(float* __restrict__ out) {
    int t = blockIdx.x;
    int i0 = g_topk_i[2 * t], i1 = g_topk_i[2 * t + 1];
    int s0 = g_slot[2 * t], s1 = g_slot[2 * t + 1];
    float w0 = g_topk_w[2 * t], w1v = g_topk_w[2 * t + 1];
    int d = threadIdx.x * 4;
    float4 a = make_float4(0.f, 0.f, 0.f, 0.f);
    if (s0 >= 0) {
        float4 v = *reinterpret_cast<const float4*>(g_oute + ((size_t)i0 * CAP + s0) * DM + d);
        a.x += w0 * v.x; a.y += w0 * v.y; a.z += w0 * v.z; a.w += w0 * v.w;
    }
    if (s1 >= 0) {
        float4 v = *reinterpret_cast<const float4*>(g_oute + ((size_t)i1 * CAP + s1) * DM + d);
        a.x += w1v * v.x; a.y += w1v * v.y; a.z += w1v * v.z; a.w += w1v * v.w;
    }
    *reinterpret_cast<float4*>(out + (size_t)t * DM + d) = a;
}

// ---------------- launch ----------------
extern "C" void kernel_launch(void* const* d_in, const int* in_sizes, int n_in,
                              void* d_out, int out_size) {
    (void)in_sizes; (void)n_in; (void)out_size;
    const float* x      = (const float*)d_in[0];
    const float* gate_w = (const float*)d_in[1];
    const float* gate_b = (const float*)d_in[2];
    const float* w1     = (const float*)d_in[3];
    const float* b1     = (const float*)d_in[4];
    const float* w2     = (const float*)d_in[5];
    const float* b2     = (const float*)d_in[6];
    float* out = (float*)d_out;

    static bool attr_done = false;
    if (!attr_done) {
        cudaFuncSetAttribute(gemm_kernel<true,  true,  DM,    FFDIM>,
                             cudaFuncAttributeMaxDynamicSharedMemorySize, SMEM_BYTES);
        cudaFuncSetAttribute(gemm_kernel<false, false, FFDIM, DM>,
                             cudaFuncAttributeMaxDynamicSharedMemorySize, SMEM_BYTES);
        attr_done = true;
    }

    // device-pointer fetch for __device__ globals (host side, capture-safe)
    static float *p_xr = nullptr, *p_w1r = nullptr, *p_w2r = nullptr;
    if (!p_xr) {
        cudaGetSymbolAddress((void**)&p_xr,  g_xr);
        cudaGetSymbolAddress((void**)&p_w1r, g_w1r);
        cudaGetSymbolAddress((void**)&p_w2r, g_w2r);
    }

    const int n4_x = S_TOK * DM / 4;
    const int n4_w = NE * DM * FFDIM / 4;

    round_kernel<<<2048, 256>>>((const float4*)x,  (float4*)p_xr,  n4_x);
    round_kernel<<<8192, 256>>>((const float4*)w1, (float4*)p_w1r, n4_w);
    round_kernel<<<8192, 256>>>((const float4*)w2, (float4*)p_w2r, n4_w);

    gate_kernel<<<S_TOK / 8, 256>>>(x, gate_w, gate_b);
    route_kernel<<<1, 256>>>();
    gemm_kernel<true,  true,  DM,    FFDIM>
        <<<dim3(FFDIM / BN, CAP / BM, NE), 256, SMEM_BYTES>>>(p_xr, p_w1r, b1);
    gemm_kernel<false, false, FFDIM, DM>
        <<<dim3(DM / BN,    CAP / BM, NE), 256, SMEM_BYTES>>>(nullptr, p_w2r, b2);
    combine_kernel<<<S_TOK, 256>>>(out);
}

// round 7
// speedup vs baseline: 1.5066x; 1.0651x over previous
#include <cuda_runtime.h>
#include <math.h>

#define S_TOK 8192
#define DM    1024
#define FFDIM 4096
#define NE    8
#define CAP   1280

#define BM 128
#define BN 128
#define BK 32
#define NSTG 3
#define A_STAGE_BYTES (BM * BK * 4)            // 16384 (128 rows x 128B)
#define STAGE_BYTES   (2 * A_STAGE_BYTES)      // 32768
#define SMEM_BYTES    (NSTG * STAGE_BYTES)     // 98304

// ---------------- scratch (device globals; no allocation allowed) ----------------
__device__ int   g_topk_i[S_TOK * 2];
__device__ float g_topk_w[S_TOK * 2];
__device__ int   g_slot[S_TOK * 2];
__device__ int   g_idx[NE * CAP];
__device__ int   g_cnt[NE];
__device__ float g_xr [(size_t)S_TOK * DM];         // tf32-rounded x (token order, K-major)
__device__ float g_w1t[(size_t)NE * FFDIM * DM];    // w1 -> [e][FF][DM] K-major, rounded
__device__ float g_w2t[(size_t)NE * DM * FFDIM];    // w2 -> [e][DM][FF] K-major, rounded
__device__ float g_h  [(size_t)NE * CAP * FFDIM];   // hidden (rounded in epilogue), K-major for GEMM2
__device__ float g_oute[(size_t)NE * CAP * DM];     // expert outputs

__device__ __forceinline__ float to_tf32(float x) {
    unsigned u;
    asm("cvt.rna.tf32.f32 %0, %1;" : "=r"(u) : "f"(x));
    return __uint_as_float(u);
}

__device__ __forceinline__ void mma_tf32(float* d, const unsigned* a, const unsigned* b) {
    asm volatile(
        "mma.sync.aligned.m16n8k8.row.col.f32.tf32.tf32.f32 "
        "{%0,%1,%2,%3}, {%4,%5,%6,%7}, {%8,%9}, {%0,%1,%2,%3};\n"
        : "+f"(d[0]), "+f"(d[1]), "+f"(d[2]), "+f"(d[3])
        : "r"(a[0]), "r"(a[1]), "r"(a[2]), "r"(a[3]), "r"(b[0]), "r"(b[1]));
}

__device__ __forceinline__ void ldsm_x4(unsigned* r, unsigned addr) {
    asm volatile("ldmatrix.sync.aligned.m8n8.x4.shared.b16 {%0,%1,%2,%3}, [%4];"
                 : "=r"(r[0]), "=r"(r[1]), "=r"(r[2]), "=r"(r[3]) : "r"(addr));
}

__device__ __forceinline__ void cp_async16(unsigned smem_addr, const void* gptr, int src_bytes) {
    asm volatile("cp.async.ca.shared.global [%0], [%1], 16, %2;\n"
                 :: "r"(smem_addr), "l"(gptr), "r"(src_bytes));
}
__device__ __forceinline__ void cp_commit() { asm volatile("cp.async.commit_group;\n"); }
__device__ __forceinline__ void cp_wait1()  { asm volatile("cp.async.wait_group 1;\n"); }

// ---------------- elementwise tf32 rounding copy ----------------
__global__ __launch_bounds__(256) void round_kernel(const float4* __restrict__ src,
                                                    float4* __restrict__ dst, int n4) {
    int i = blockIdx.x * 256 + threadIdx.x;
    int stride = gridDim.x * 256;
    for (; i < n4; i += stride) {
        float4 v = src[i];
        v.x = to_tf32(v.x); v.y = to_tf32(v.y); v.z = to_tf32(v.z); v.w = to_tf32(v.w);
        dst[i] = v;
    }
}

// ---------------- transpose + round weights: src[e][R][C] -> dst[e][C][R] ----------------
template<bool W1>
__global__ __launch_bounds__(256) void wtr_kernel(const float* __restrict__ src) {
    constexpr int R = W1 ? DM : FFDIM;
    constexpr int C = W1 ? FFDIM : DM;
    float* dst = W1 ? g_w1t : g_w2t;
    __shared__ float tile[32][33];
    int e = blockIdx.z;
    int c0 = blockIdx.x * 32, r0 = blockIdx.y * 32;
    const float* s = src + (size_t)e * R * C;
    float* d = dst + (size_t)e * R * C;
    int tx = threadIdx.x & 31, ty = threadIdx.x >> 5;
#pragma unroll
    for (int i = 0; i < 32; i += 8)
        tile[ty + i][tx] = s[(size_t)(r0 + ty + i) * C + c0 + tx];
    __syncthreads();
#pragma unroll
    for (int i = 0; i < 32; i += 8)
        d[(size_t)(c0 + ty + i) * R + r0 + tx] = to_tf32(tile[tx][ty + i]);
}

// ---------------- gating ----------------
__global__ __launch_bounds__(256) void gate_kernel(const float* __restrict__ x,
                                                   const float* __restrict__ gw,
                                                   const float* __restrict__ gb) {
    __shared__ float sgw[DM * 9];
    int tid = threadIdx.x;
    for (int i = tid; i < DM * NE; i += 256) sgw[(i >> 3) * 9 + (i & 7)] = gw[i];
    __syncthreads();

    int warp = tid >> 5, lane = tid & 31;
    int t = blockIdx.x * 8 + warp;
    const float* xr = x + (size_t)t * DM;
    float acc[NE];
#pragma unroll
    for (int e = 0; e < NE; e++) acc[e] = 0.f;
    for (int d = lane; d < DM; d += 32) {
        float xv = xr[d];
        const float* g = &sgw[d * 9];
#pragma unroll
        for (int e = 0; e < NE; e++) acc[e] += xv * g[e];
    }
#pragma unroll
    for (int e = 0; e < NE; e++) {
#pragma unroll
        for (int off = 16; off; off >>= 1)
            acc[e] += __shfl_xor_sync(0xffffffffu, acc[e], off);
    }
    if (lane == 0) {
        float l[NE];
#pragma unroll
        for (int e = 0; e < NE; e++) l[e] = acc[e] + gb[e];
        int i0 = 0;
#pragma unroll
        for (int e = 1; e < NE; e++) if (l[e] > l[i0]) i0 = e;
        int i1 = (i0 == 0) ? 1 : 0;
#pragma unroll
        for (int e = 0; e < NE; e++) if (e != i0 && l[e] > l[i1]) i1 = e;
        float p1 = expf(l[i1] - l[i0]);
        float w0 = 1.f / (1.f + p1);
        g_topk_i[2 * t] = i0; g_topk_i[2 * t + 1] = i1;
        g_topk_w[2 * t] = w0; g_topk_w[2 * t + 1] = 1.f - w0;
    }
}

// ---------------- routing ----------------
__global__ __launch_bounds__(256) void route_kernel() {
    __shared__ int wsum[8];
    __shared__ int run[NE];
    int tid = threadIdx.x, lane = tid & 31, warp = tid >> 5;
    if (tid < NE) run[tid] = 0;
    __syncthreads();

    for (int base = 0; base < S_TOK; base += 256) {
        int t = base + tid;
        int i0 = g_topk_i[2 * t], i1 = g_topk_i[2 * t + 1];
        int rank0 = 0, rank1 = 0;
        for (int e = 0; e < NE; e++) {
            int v = (i0 == e || i1 == e) ? 1 : 0;
#pragma unroll
            for (int off = 1; off < 32; off <<= 1) {
                int u = __shfl_up_sync(0xffffffffu, v, off);
                if (lane >= off) v += u;
            }
            if (lane == 31) wsum[warp] = v;
            __syncthreads();
            int woff = 0, total = 0;
#pragma unroll
            for (int w = 0; w < 8; w++) { int s = wsum[w]; total += s; if (w < warp) woff += s; }
            int rank = run[e] + woff + v;
            if (i0 == e) rank0 = rank;
            if (i1 == e) rank1 = rank;
            __syncthreads();
            if (tid == 0) run[e] += total;
        }
        int s0 = (rank0 <= CAP) ? rank0 - 1 : -1;
        int s1 = (rank1 <= CAP) ? rank1 - 1 : -1;
        g_slot[2 * t] = s0; g_slot[2 * t + 1] = s1;
        if (s0 >= 0) g_idx[i0 * CAP + s0] = t;
        if (s1 >= 0) g_idx[i1 * CAP + s1] = t;
    }
    __syncthreads();
    if (tid < NE) g_cnt[tid] = min(run[tid], CAP);
}

// ---------------- expert GEMM: tf32 mma.sync + ldmatrix + 3-stage cp.async ----------------
// Both operands K-major (rows x BK=32 floats = 128B), 16B-granule XOR swizzle c^(r&7).
// 8 warps 2x4, warp tile 64x32. GATHER: A rows via g_idx from g_xr (zeros if invalid).
template<bool GATHER, bool RELU, int KDIM, int NDIM>
__global__ __launch_bounds__(256, 2)
void gemm_kernel(const float* __restrict__ Aglob,
                 const float* __restrict__ Wglob,
                 const float* __restrict__ biasGlob) {
    extern __shared__ char smem[];
    __shared__ int sTok[BM];

    const int e = blockIdx.z;
    const int rowBase = blockIdx.y * BM;
    const int nBase = blockIdx.x * BN;
    const int tid = threadIdx.x;

    const float* Abase = GATHER ? Aglob : (g_h + (size_t)e * CAP * KDIM);
    const float* W = Wglob + ((size_t)e * NDIM + nBase) * KDIM;
    const float* bias = biasGlob + e * NDIM;
    float* Out = (RELU ? g_h : g_oute) + (size_t)e * CAP * NDIM;

    if (tid < BM) {
        int r = rowBase + tid;
        sTok[tid] = GATHER ? ((r < g_cnt[e]) ? g_idx[e * CAP + r] : -1) : (rowBase + tid);
    }
    __syncthreads();

    const unsigned smem_base = (unsigned)__cvta_generic_to_shared(smem);

    // loader: 128 rows x 8 granules (16B) per operand; 256 threads -> 4 granules each
    const int ldRow0 = tid >> 2;            // 0..63 (+64 second pass)
    const int ldC0 = tid & 3;               // granules c and c+4

    auto load_stage = [&](int slot, int kk) {
        unsigned aB = smem_base + slot * STAGE_BYTES;
        unsigned bB = aB + A_STAGE_BYTES;
#pragma unroll
        for (int i = 0; i < 2; i++) {
            int row = ldRow0 + i * 64;
            int r7 = row & 7;
            int tok = sTok[row];
            const float* asrc = Abase + (size_t)((tok < 0) ? 0 : tok) * KDIM + kk;
            const float* bsrc = W + (size_t)row * KDIM + kk;
#pragma unroll
            for (int j = 0; j < 2; j++) {
                int c = ldC0 + j * 4;
                unsigned sw = (unsigned)(row * 128 + ((c ^ r7) << 4));
                cp_async16(aB + sw, asrc + c * 4, (tok >= 0) ? 16 : 0);
                cp_async16(bB + sw, bsrc + c * 4, 16);
            }
        }
    };

    float acc[4][4][4];
#pragma unroll
    for (int mt = 0; mt < 4; mt++)
#pragma unroll
        for (int nt = 0; nt < 4; nt++)
#pragma unroll
            for (int i = 0; i < 4; i++) acc[mt][nt][i] = 0.f;

    const int warp = tid >> 5, lane = tid & 31;
    const int wm = warp >> 2, wn = warp & 3;       // 2x4 grid, warp tile 64x32
    const int t4 = lane >> 3;                      // ldmatrix tile index 0..3
    const int row7 = lane & 7;

    // ldmatrix lane row bases (bytes within operand stage)
    const int aRowByte = (wm * 64 + (t4 & 1) * 8 + row7) * 128;   // + mt*16*128
    const int aG = (t4 >> 1);                                     // + kf/4
    const int bRowByte = (wn * 32 + (t4 >> 1) * 8 + row7) * 128;  // + ntp*16*128
    const int bG = (t4 & 1);                                      // + kf/4

    const int NIT = KDIM / BK;

    load_stage(0, 0); cp_commit();
    load_stage(1, BK); cp_commit();

    int slot = 0, nslot = 2;
    for (int k = 0; k < NIT; k++) {
        cp_wait1();
        __syncthreads();

        int nk = k + 2;
        if (nk < NIT) load_stage(nslot, nk * BK);
        cp_commit();

        const unsigned sA = smem_base + slot * STAGE_BYTES;
        const unsigned sB = sA + A_STAGE_BYTES;

#pragma unroll
        for (int kf = 0; kf < BK; kf += 8) {
            const int g4 = kf >> 2;
            unsigned a[4][4], b[4][2];
#pragma unroll
            for (int mt = 0; mt < 4; mt++)
                ldsm_x4(a[mt], sA + aRowByte + mt * 2048 + (((g4 + aG) ^ row7) << 4));
#pragma unroll
            for (int ntp = 0; ntp < 2; ntp++) {
                unsigned r[4];
                ldsm_x4(r, sB + bRowByte + ntp * 2048 + (((g4 + bG) ^ row7) << 4));
                b[2 * ntp][0] = r[0]; b[2 * ntp][1] = r[1];
                b[2 * ntp + 1][0] = r[2]; b[2 * ntp + 1][1] = r[3];
            }
#pragma unroll
            for (int mt = 0; mt < 4; mt++)
#pragma unroll
                for (int nt = 0; nt < 4; nt++)
                    mma_tf32(acc[mt][nt], a[mt], b[nt]);
        }
        slot = (slot == NSTG - 1) ? 0 : slot + 1;
        nslot = (nslot == NSTG - 1) ? 0 : nslot + 1;
    }

    // epilogue: + bias (, relu + round), store
    const int gid = lane >> 2, tig = lane & 3;
#pragma unroll
    for (int mt = 0; mt < 4; mt++) {
        int r0 = rowBase + wm * 64 + mt * 16 + gid;
#pragma unroll
        for (int nt = 0; nt < 4; nt++) {
            int c = nBase + wn * 32 + nt * 8 + 2 * tig;
            float bv0 = bias[c], bv1 = bias[c + 1];
            float v00 = acc[mt][nt][0] + bv0;
            float v01 = acc[mt][nt][1] + bv1;
            float v10 = acc[mt][nt][2] + bv0;
            float v11 = acc[mt][nt][3] + bv1;
            if (RELU) {
                v00 = to_tf32(fmaxf(v00, 0.f)); v01 = to_tf32(fmaxf(v01, 0.f));
                v10 = to_tf32(fmaxf(v10, 0.f)); v11 = to_tf32(fmaxf(v11, 0.f));
            }
            *reinterpret_cast<float2*>(Out + (size_t)r0 * NDIM + c) = make_float2(v00, v01);
            *reinterpret_cast<float2*>(Out + (size_t)(r0 + 8) * NDIM + c) = make_float2(v10, v11);
        }
    }
}

// ---------------- combine ----------------
__global__ __launch_bounds__(256) void combine_kernel(float* __restrict__ out) {
    int t = blockIdx.x;
    int i0 = g_topk_i[2 * t], i1 = g_topk_i[2 * t + 1];
    int s0 = g_slot[2 * t], s1 = g_slot[2 * t + 1];
    float w0 = g_topk_w[2 * t], w1v = g_topk_w[2 * t + 1];
    int d = threadIdx.x * 4;
    float4 a = make_float4(0.f, 0.f, 0.f, 0.f);
    if (s0 >= 0) {
        float4 v = *reinterpret_cast<const float4*>(g_oute + ((size_t)i0 * CAP + s0) * DM + d);
        a.x += w0 * v.x; a.y += w0 * v.y; a.z += w0 * v.z; a.w += w0 * v.w;
    }
    if (s1 >= 0) {
        float4 v = *reinterpret_cast<const float4*>(g_oute + ((size_t)i1 * CAP + s1) * DM + d);
        a.x += w1v * v.x; a.y += w1v * v.y; a.z += w1v * v.z; a.w += w1v * v.w;
    }
    *reinterpret_cast<float4*>(out + (size_t)t * DM + d) = a;
}

// ---------------- launch ----------------
extern "C" void kernel_launch(void* const* d_in, const int* in_sizes, int n_in,
                              void* d_out, int out_size) {
    (void)in_sizes; (void)n_in; (void)out_size;
    const float* x      = (const float*)d_in[0];
    const float* gate_w = (const float*)d_in[1];
    const float* gate_b = (const float*)d_in[2];
    const float* w1     = (const float*)d_in[3];
    const float* b1     = (const float*)d_in[4];
    const float* w2     = (const float*)d_in[5];
    const float* b2     = (const float*)d_in[6];
    float* out = (float*)d_out;

    static bool attr_done = false;
    if (!attr_done) {
        cudaFuncSetAttribute(gemm_kernel<true,  true,  DM,    FFDIM>,
                             cudaFuncAttributeMaxDynamicSharedMemorySize, SMEM_BYTES);
        cudaFuncSetAttribute(gemm_kernel<false, false, FFDIM, DM>,
                             cudaFuncAttributeMaxDynamicSharedMemorySize, SMEM_BYTES);
        attr_done = true;
    }

    static float *p_xr = nullptr, *p_w1t = nullptr, *p_w2t = nullptr;
    if (!p_xr) {
        cudaGetSymbolAddress((void**)&p_xr,  g_xr);
        cudaGetSymbolAddress((void**)&p_w1t, g_w1t);
        cudaGetSymbolAddress((void**)&p_w2t, g_w2t);
    }

    round_kernel<<<2048, 256>>>((const float4*)x, (float4*)p_xr, S_TOK * DM / 4);
    wtr_kernel<true ><<<dim3(FFDIM / 32, DM / 32, NE), 256>>>(w1);
    wtr_kernel<false><<<dim3(DM / 32, FFDIM / 32, NE), 256>>>(w2);

    gate_kernel<<<S_TOK / 8, 256>>>(x, gate_w, gate_b);
    route_kernel<<<1, 256>>>();
    gemm_kernel<true,  true,  DM,    FFDIM>
        <<<dim3(FFDIM / BN, CAP / BM, NE), 256, SMEM_BYTES>>>(p_xr, p_w1t, b1);
    gemm_kernel<false, false, FFDIM, DM>
        <<<dim3(DM / BN,    CAP / BM, NE), 256, SMEM_BYTES>>>(nullptr, p_w2t, b2);
    combine_kernel<<<S_TOK, 256>>>(out);
}

// round 8
// speedup vs baseline: 2.6166x; 1.7367x over previous
#include <cuda_runtime.h>
#include <cuda_fp16.h>
#include <math.h>

#define S_TOK 8192
#define DM    1024
#define FFDIM 4096
#define NE    8
#define CAP   1280

#define BM 128
#define BN 128
#define BKH 64                                 // K halves per stage (128B row)
#define NSTG 3
#define A_STAGE_BYTES (BM * 128)               // 16384
#define STAGE_BYTES   (2 * A_STAGE_BYTES)      // 32768
#define SMEM_BYTES    (NSTG * STAGE_BYTES)     // 98304

// ---------------- scratch (device globals; no allocation allowed) ----------------
__device__ int    g_topk_i[S_TOK * 2];
__device__ float  g_topk_w[S_TOK * 2];
__device__ int    g_slot[S_TOK * 2];
__device__ int    g_idx[NE * CAP];
__device__ int    g_cnt[NE];
__device__ __half g_xh [(size_t)S_TOK * DM];        // fp16 x (token order, K-major)
__device__ __half g_w1h[(size_t)NE * FFDIM * DM];   // w1 -> [e][FF][DM] K-major fp16
__device__ __half g_w2h[(size_t)NE * DM * FFDIM];   // w2 -> [e][DM][FF] K-major fp16
__device__ __half g_h  [(size_t)NE * CAP * FFDIM];  // hidden fp16 (K-major for GEMM2)
__device__ float  g_oute[(size_t)NE * CAP * DM];    // expert outputs fp32

__device__ __forceinline__ void mma_f16(float* d, const unsigned* a, const unsigned* b) {
    asm volatile(
        "mma.sync.aligned.m16n8k16.row.col.f32.f16.f16.f32 "
        "{%0,%1,%2,%3}, {%4,%5,%6,%7}, {%8,%9}, {%0,%1,%2,%3};\n"
        : "+f"(d[0]), "+f"(d[1]), "+f"(d[2]), "+f"(d[3])
        : "r"(a[0]), "r"(a[1]), "r"(a[2]), "r"(a[3]), "r"(b[0]), "r"(b[1]));
}

__device__ __forceinline__ void ldsm_x4(unsigned* r, unsigned addr) {
    asm volatile("ldmatrix.sync.aligned.m8n8.x4.shared.b16 {%0,%1,%2,%3}, [%4];"
                 : "=r"(r[0]), "=r"(r[1]), "=r"(r[2]), "=r"(r[3]) : "r"(addr));
}

__device__ __forceinline__ void cp_async16(unsigned smem_addr, const void* gptr, int src_bytes) {
    asm volatile("cp.async.ca.shared.global [%0], [%1], 16, %2;\n"
                 :: "r"(smem_addr), "l"(gptr), "r"(src_bytes));
}
__device__ __forceinline__ void cp_commit() { asm volatile("cp.async.commit_group;\n"); }
__device__ __forceinline__ void cp_wait1()  { asm volatile("cp.async.wait_group 1;\n"); }

// ---------------- convert x -> fp16 ----------------
__global__ __launch_bounds__(256) void xh_kernel(const float4* __restrict__ src,
                                                 __half2* __restrict__ dst, int n4) {
    int i = blockIdx.x * 256 + threadIdx.x;
    int stride = gridDim.x * 256;
    for (; i < n4; i += stride) {
        float4 v = src[i];
        dst[2 * i]     = __floats2half2_rn(v.x, v.y);
        dst[2 * i + 1] = __floats2half2_rn(v.z, v.w);
    }
}

// ---------------- transpose + convert weights: src[e][R][C] -> dst[e][C][R] fp16 ----------------
template<bool W1>
__global__ __launch_bounds__(256) void wtr_kernel(const float* __restrict__ src) {
    constexpr int R = W1 ? DM : FFDIM;
    constexpr int C = W1 ? FFDIM : DM;
    __half* dst = W1 ? g_w1h : g_w2h;
    __shared__ float tile[32][33];
    int e = blockIdx.z;
    int c0 = blockIdx.x * 32, r0 = blockIdx.y * 32;
    const float* s = src + (size_t)e * R * C;
    __half* d = dst + (size_t)e * R * C;
    int tx = threadIdx.x & 31, ty = threadIdx.x >> 5;
#pragma unroll
    for (int i = 0; i < 32; i += 8)
        tile[ty + i][tx] = s[(size_t)(r0 + ty + i) * C + c0 + tx];
    __syncthreads();
#pragma unroll
    for (int i = 0; i < 32; i += 8)
        d[(size_t)(c0 + ty + i) * R + r0 + tx] = __float2half_rn(tile[tx][ty + i]);
}

// ---------------- gating ----------------
__global__ __launch_bounds__(256) void gate_kernel(const float* __restrict__ x,
                                                   const float* __restrict__ gw,
                                                   const float* __restrict__ gb) {
    __shared__ float sgw[DM * 9];
    int tid = threadIdx.x;
    for (int i = tid; i < DM * NE; i += 256) sgw[(i >> 3) * 9 + (i & 7)] = gw[i];
    __syncthreads();

    int warp = tid >> 5, lane = tid & 31;
    int t = blockIdx.x * 8 + warp;
    const float* xr = x + (size_t)t * DM;
    float acc[NE];
#pragma unroll
    for (int e = 0; e < NE; e++) acc[e] = 0.f;
    for (int d = lane; d < DM; d += 32) {
        float xv = xr[d];
        const float* g = &sgw[d * 9];
#pragma unroll
        for (int e = 0; e < NE; e++) acc[e] += xv * g[e];
    }
#pragma unroll
    for (int e = 0; e < NE; e++) {
#pragma unroll
        for (int off = 16; off; off >>= 1)
            acc[e] += __shfl_xor_sync(0xffffffffu, acc[e], off);
    }
    if (lane == 0) {
        float l[NE];
#pragma unroll
        for (int e = 0; e < NE; e++) l[e] = acc[e] + gb[e];
        int i0 = 0;
#pragma unroll
        for (int e = 1; e < NE; e++) if (l[e] > l[i0]) i0 = e;
        int i1 = (i0 == 0) ? 1 : 0;
#pragma unroll
        for (int e = 0; e < NE; e++) if (e != i0 && l[e] > l[i1]) i1 = e;
        float p1 = expf(l[i1] - l[i0]);
        float w0 = 1.f / (1.f + p1);
        g_topk_i[2 * t] = i0; g_topk_i[2 * t + 1] = i1;
        g_topk_w[2 * t] = w0; g_topk_w[2 * t + 1] = 1.f - w0;
    }
}

// ---------------- routing ----------------
__global__ __launch_bounds__(256) void route_kernel() {
    __shared__ int wsum[8];
    __shared__ int run[NE];
    int tid = threadIdx.x, lane = tid & 31, warp = tid >> 5;
    if (tid < NE) run[tid] = 0;
    __syncthreads();

    for (int base = 0; base < S_TOK; base += 256) {
        int t = base + tid;
        int i0 = g_topk_i[2 * t], i1 = g_topk_i[2 * t + 1];
        int rank0 = 0, rank1 = 0;
        for (int e = 0; e < NE; e++) {
            int v = (i0 == e || i1 == e) ? 1 : 0;
#pragma unroll
            for (int off = 1; off < 32; off <<= 1) {
                int u = __shfl_up_sync(0xffffffffu, v, off);
                if (lane >= off) v += u;
            }
            if (lane == 31) wsum[warp] = v;
            __syncthreads();
            int woff = 0, total = 0;
#pragma unroll
            for (int w = 0; w < 8; w++) { int s = wsum[w]; total += s; if (w < warp) woff += s; }
            int rank = run[e] + woff + v;
            if (i0 == e) rank0 = rank;
            if (i1 == e) rank1 = rank;
            __syncthreads();
            if (tid == 0) run[e] += total;
        }
        int s0 = (rank0 <= CAP) ? rank0 - 1 : -1;
        int s1 = (rank1 <= CAP) ? rank1 - 1 : -1;
        g_slot[2 * t] = s0; g_slot[2 * t + 1] = s1;
        if (s0 >= 0) g_idx[i0 * CAP + s0] = t;
        if (s1 >= 0) g_idx[i1 * CAP + s1] = t;
    }
    __syncthreads();
    if (tid < NE) g_cnt[tid] = min(run[tid], CAP);
}

// ---------------- expert GEMM: fp16 mma.sync m16n8k16 + ldmatrix + 3-stage cp.async ----------------
// Operands K-major, rows of 64 halves = 128B, 16B-granule swizzle c^(r&7).
// 8 warps 2x4, warp tile 64x32. Per k16 group: 4 A ldsm.x4 + 2 B ldsm.x4 + 16 HMMA.
template<bool GATHER, bool RELU, int KDIM, int NDIM>
__global__ __launch_bounds__(256, 2)
void gemm_kernel(const __half* __restrict__ Aglob,
                 const __half* __restrict__ Wglob,
                 const float* __restrict__ biasGlob) {
    extern __shared__ char smem[];
    __shared__ int sTok[BM];

    const int e = blockIdx.z;
    const int rowBase = blockIdx.y * BM;
    const int nBase = blockIdx.x * BN;
    const int tid = threadIdx.x;

    const __half* Abase = GATHER ? Aglob : (g_h + (size_t)e * CAP * KDIM);
    const __half* W = Wglob + ((size_t)e * NDIM + nBase) * KDIM;
    const float* bias = biasGlob + e * NDIM;

    if (tid < BM) {
        int r = rowBase + tid;
        sTok[tid] = GATHER ? ((r < g_cnt[e]) ? g_idx[e * CAP + r] : -1) : (rowBase + tid);
    }
    __syncthreads();

    const unsigned smem_base = (unsigned)__cvta_generic_to_shared(smem);

    // loader: 128 rows x 8 granules (16B) per operand; 256 threads -> 4 granules each
    const int ldRow0 = tid >> 2;
    const int ldC0 = tid & 3;

    auto load_stage = [&](int slot, int kk) {    // kk in halves
        unsigned aB = smem_base + slot * STAGE_BYTES;
        unsigned bB = aB + A_STAGE_BYTES;
#pragma unroll
        for (int i = 0; i < 2; i++) {
            int row = ldRow0 + i * 64;
            int r7 = row & 7;
            int tok = sTok[row];
            const __half* asrc = Abase + (size_t)((tok < 0) ? 0 : tok) * KDIM + kk;
            const __half* bsrc = W + (size_t)row * KDIM + kk;
#pragma unroll
            for (int j = 0; j < 2; j++) {
                int c = ldC0 + j * 4;
                unsigned sw = (unsigned)(row * 128 + ((c ^ r7) << 4));
                cp_async16(aB + sw, asrc + c * 8, (tok >= 0) ? 16 : 0);
                cp_async16(bB + sw, bsrc + c * 8, 16);
            }
        }
    };

    float acc[4][4][4];
#pragma unroll
    for (int mt = 0; mt < 4; mt++)
#pragma unroll
        for (int nt = 0; nt < 4; nt++)
#pragma unroll
            for (int i = 0; i < 4; i++) acc[mt][nt][i] = 0.f;

    const int warp = tid >> 5, lane = tid & 31;
    const int wm = warp >> 2, wn = warp & 3;       // 2x4 grid, warp tile 64x32
    const int t4 = lane >> 3;
    const int row7 = lane & 7;

    // A ldsm.x4: m0=rows0-7 g0, m1=rows8-15 g0, m2=rows0-7 g1, m3=rows8-15 g1
    const int aRowByte = (wm * 64 + (t4 & 1) * 8 + row7) * 128;
    const int aG = (t4 >> 1);
    // B ldsm.x4: m0=n0-7 g0, m1=n0-7 g1, m2=n8-15 g0, m3=n8-15 g1
    const int bRowByte = (wn * 32 + (t4 >> 1) * 8 + row7) * 128;
    const int bG = (t4 & 1);

    const int NIT = KDIM / BKH;

    load_stage(0, 0); cp_commit();
    load_stage(1, BKH); cp_commit();

    int slot = 0, nslot = 2;
    for (int k = 0; k < NIT; k++) {
        cp_wait1();
        __syncthreads();

        int nk = k + 2;
        if (nk < NIT) load_stage(nslot, nk * BKH);
        cp_commit();

        const unsigned sA = smem_base + slot * STAGE_BYTES;
        const unsigned sB = sA + A_STAGE_BYTES;

#pragma unroll
        for (int gr = 0; gr < 4; gr++) {           // k16 groups within BKH=64
            unsigned a[4][4], b[4][2];
#pragma unroll
            for (int mt = 0; mt < 4; mt++)
                ldsm_x4(a[mt], sA + aRowByte + mt * 2048 + ((((2 * gr) + aG) ^ row7) << 4));
#pragma unroll
            for (int ntp = 0; ntp < 2; ntp++) {
                unsigned r[4];
                ldsm_x4(r, sB + bRowByte + ntp * 2048 + ((((2 * gr) + bG) ^ row7) << 4));
                b[2 * ntp][0] = r[0]; b[2 * ntp][1] = r[1];
                b[2 * ntp + 1][0] = r[2]; b[2 * ntp + 1][1] = r[3];
            }
#pragma unroll
            for (int mt = 0; mt < 4; mt++)
#pragma unroll
                for (int nt = 0; nt < 4; nt++)
                    mma_f16(acc[mt][nt], a[mt], b[nt]);
        }
        slot = (slot == NSTG - 1) ? 0 : slot + 1;
        nslot = (nslot == NSTG - 1) ? 0 : nslot + 1;
    }

    // epilogue
    const int gid = lane >> 2, tig = lane & 3;
#pragma unroll
    for (int mt = 0; mt < 4; mt++) {
        int r0 = rowBase + wm * 64 + mt * 16 + gid;
#pragma unroll
        for (int nt = 0; nt < 4; nt++) {
            int c = nBase + wn * 32 + nt * 8 + 2 * tig;
            float bv0 = bias[c], bv1 = bias[c + 1];
            float v00 = acc[mt][nt][0] + bv0;
            float v01 = acc[mt][nt][1] + bv1;
            float v10 = acc[mt][nt][2] + bv0;
            float v11 = acc[mt][nt][3] + bv1;
            if (RELU) {
                __half* OutH = g_h + (size_t)e * CAP * NDIM;
                *reinterpret_cast<__half2*>(OutH + (size_t)r0 * NDIM + c) =
                    __floats2half2_rn(fmaxf(v00, 0.f), fmaxf(v01, 0.f));
                *reinterpret_cast<__half2*>(OutH + (size_t)(r0 + 8) * NDIM + c) =
                    __floats2half2_rn(fmaxf(v10, 0.f), fmaxf(v11, 0.f));
            } else {
                float* OutF = g_oute + (size_t)e * CAP * NDIM;
                *reinterpret_cast<float2*>(OutF + (size_t)r0 * NDIM + c) = make_float2(v00, v01);
                *reinterpret_cast<float2*>(OutF + (size_t)(r0 + 8) * NDIM + c) = make_float2(v10, v11);
            }
        }
    }
}

// ---------------- combine ----------------
__global__ __launch_bounds__(256) void combine_kernel(float* __restrict__ out) {
    int t = blockIdx.x;
    int i0 = g_topk_i[2 * t], i1 = g_topk_i[2 * t + 1];
    int s0 = g_slot[2 * t], s1 = g_slot[2 * t + 1];
    float w0 = g_topk_w[2 * t], w1v = g_topk_w[2 * t + 1];
    int d = threadIdx.x * 4;
    float4 a = make_float4(0.f, 0.f, 0.f, 0.f);
    if (s0 >= 0) {
        float4 v = *reinterpret_cast<const float4*>(g_oute + ((size_t)i0 * CAP + s0) * DM + d);
        a.x += w0 * v.x; a.y += w0 * v.y; a.z += w0 * v.z; a.w += w0 * v.w;
    }
    if (s1 >= 0) {
        float4 v = *reinterpret_cast<const float4*>(g_oute + ((size_t)i1 * CAP + s1) * DM + d);
        a.x += w1v * v.x; a.y += w1v * v.y; a.z += w1v * v.z; a.w += w1v * v.w;
    }
    *reinterpret_cast<float4*>(out + (size_t)t * DM + d) = a;
}

// ---------------- launch ----------------
extern "C" void kernel_launch(void* const* d_in, const int* in_sizes, int n_in,
                              void* d_out, int out_size) {
    (void)in_sizes; (void)n_in; (void)out_size;
    const float* x      = (const float*)d_in[0];
    const float* gate_w = (const float*)d_in[1];
    const float* gate_b = (const float*)d_in[2];
    const float* w1     = (const float*)d_in[3];
    const float* b1     = (const float*)d_in[4];
    const float* w2     = (const float*)d_in[5];
    const float* b2     = (const float*)d_in[6];
    float* out = (float*)d_out;

    static bool attr_done = false;
    if (!attr_done) {
        cudaFuncSetAttribute(gemm_kernel<true,  true,  DM,    FFDIM>,
                             cudaFuncAttributeMaxDynamicSharedMemorySize, SMEM_BYTES);
        cudaFuncSetAttribute(gemm_kernel<false, false, FFDIM, DM>,
                             cudaFuncAttributeMaxDynamicSharedMemorySize, SMEM_BYTES);
        attr_done = true;
    }

    static __half *p_xh = nullptr, *p_w1h = nullptr, *p_w2h = nullptr;
    if (!p_xh) {
        cudaGetSymbolAddress((void**)&p_xh,  g_xh);
        cudaGetSymbolAddress((void**)&p_w1h, g_w1h);
        cudaGetSymbolAddress((void**)&p_w2h, g_w2h);
    }

    xh_kernel<<<2048, 256>>>((const float4*)x, (__half2*)p_xh, S_TOK * DM / 4);
    wtr_kernel<true ><<<dim3(FFDIM / 32, DM / 32, NE), 256>>>(w1);
    wtr_kernel<false><<<dim3(DM / 32, FFDIM / 32, NE), 256>>>(w2);

    gate_kernel<<<S_TOK / 8, 256>>>(x, gate_w, gate_b);
    route_kernel<<<1, 256>>>();
    gemm_kernel<true,  true,  DM,    FFDIM>
        <<<dim3(FFDIM / BN, CAP / BM, NE), 256, SMEM_BYTES>>>(p_xh, p_w1h, b1);
    gemm_kernel<false, false, FFDIM, DM>
        <<<dim3(DM / BN,    CAP / BM, NE), 256, SMEM_BYTES>>>(nullptr, p_w2h, b2);
    combine_kernel<<<S_TOK, 256>>>(out);
}

// round 9
// speedup vs baseline: 2.8257x; 1.0799x over previous
#include <cuda_runtime.h>
#include <cuda_fp16.h>
#include <math.h>

#define S_TOK 8192
#define DM    1024
#define FFDIM 4096
#define NE    8
#define CAP   1280
#define NCHUNK 32                              // routing chunks of 256 tokens

#define BM 128
#define BN 128
#define BKH 64                                 // K halves per stage (128B row)
#define NSTG 3
#define A_STAGE_BYTES (BM * 128)               // 16384
#define STAGE_BYTES   (2 * A_STAGE_BYTES)      // 32768
#define SMEM_BYTES    (NSTG * STAGE_BYTES)     // 98304

// ---------------- scratch (device globals; no allocation allowed) ----------------
__device__ int    g_topk_i[S_TOK * 2];
__device__ float  g_topk_w[S_TOK * 2];
__device__ int    g_slot[S_TOK * 2];
__device__ int    g_lrank[S_TOK * 2];           // local (in-chunk) 1-based ranks
__device__ int    g_ccnt[NCHUNK * NE];          // per-chunk per-expert counts
__device__ int    g_coff[NCHUNK * NE];          // exclusive chunk offsets
__device__ int    g_idx[NE * CAP];
__device__ int    g_cnt[NE];
__device__ __half g_xh [(size_t)S_TOK * DM];        // fp16 x (token order, K-major)
__device__ __half g_w1h[(size_t)NE * FFDIM * DM];   // w1 -> [e][FF][DM] K-major fp16
__device__ __half g_w2h[(size_t)NE * DM * FFDIM];   // w2 -> [e][DM][FF] K-major fp16
__device__ __half g_h  [(size_t)NE * CAP * FFDIM];  // hidden fp16 (K-major for GEMM2)
__device__ float  g_oute[(size_t)NE * CAP * DM];    // expert outputs fp32

__device__ __forceinline__ void mma_f16(float* d, const unsigned* a, const unsigned* b) {
    asm volatile(
        "mma.sync.aligned.m16n8k16.row.col.f32.f16.f16.f32 "
        "{%0,%1,%2,%3}, {%4,%5,%6,%7}, {%8,%9}, {%0,%1,%2,%3};\n"
        : "+f"(d[0]), "+f"(d[1]), "+f"(d[2]), "+f"(d[3])
        : "r"(a[0]), "r"(a[1]), "r"(a[2]), "r"(a[3]), "r"(b[0]), "r"(b[1]));
}

__device__ __forceinline__ void ldsm_x4(unsigned* r, unsigned addr) {
    asm volatile("ldmatrix.sync.aligned.m8n8.x4.shared.b16 {%0,%1,%2,%3}, [%4];"
                 : "=r"(r[0]), "=r"(r[1]), "=r"(r[2]), "=r"(r[3]) : "r"(addr));
}

__device__ __forceinline__ void cp_async16(unsigned smem_addr, const void* gptr, int src_bytes) {
    asm volatile("cp.async.ca.shared.global [%0], [%1], 16, %2;\n"
                 :: "r"(smem_addr), "l"(gptr), "r"(src_bytes));
}
__device__ __forceinline__ void cp_commit() { asm volatile("cp.async.commit_group;\n"); }
__device__ __forceinline__ void cp_wait1()  { asm volatile("cp.async.wait_group 1;\n"); }

// ---------------- convert x -> fp16 ----------------
__global__ __launch_bounds__(256) void xh_kernel(const float4* __restrict__ src,
                                                 __half2* __restrict__ dst, int n4) {
    int i = blockIdx.x * 256 + threadIdx.x;
    int stride = gridDim.x * 256;
    for (; i < n4; i += stride) {
        float4 v = src[i];
        dst[2 * i]     = __floats2half2_rn(v.x, v.y);
        dst[2 * i + 1] = __floats2half2_rn(v.z, v.w);
    }
}

// ---------------- transpose + convert weights: src[e][R][C] -> dst[e][C][R] fp16 ----------------
// 64(r) x 32(c) tile; coalesced 128B reads; half2 writes covering 128B output rows.
template<bool W1>
__global__ __launch_bounds__(256) void wtr_kernel(const float* __restrict__ src) {
    constexpr int R = W1 ? DM : FFDIM;
    constexpr int C = W1 ? FFDIM : DM;
    __half* dst = W1 ? g_w1h : g_w2h;
    __shared__ float b[32][65];                 // b[c][r]
    int e = blockIdx.z;
    int c0 = blockIdx.x * 32, r0 = blockIdx.y * 64;
    const float* s = src + (size_t)e * R * C;
    __half* d = dst + (size_t)e * R * C;
    int lane = threadIdx.x & 31, w = threadIdx.x >> 5;
#pragma unroll
    for (int i = 0; i < 8; i++) {
        int r = w * 8 + i;
        b[lane][r] = s[(size_t)(r0 + r) * C + c0 + lane];
    }
    __syncthreads();
#pragma unroll
    for (int i = 0; i < 4; i++) {
        int c = w + 8 * i;
        __half2 h = __floats2half2_rn(b[c][2 * lane], b[c][2 * lane + 1]);
        *reinterpret_cast<__half2*>(d + (size_t)(c0 + c) * R + r0 + 2 * lane) = h;
    }
}

// ---------------- gating ----------------
__global__ __launch_bounds__(256) void gate_kernel(const float* __restrict__ x,
                                                   const float* __restrict__ gw,
                                                   const float* __restrict__ gb) {
    __shared__ float sgw[DM * 9];
    int tid = threadIdx.x;
    for (int i = tid; i < DM * NE; i += 256) sgw[(i >> 3) * 9 + (i & 7)] = gw[i];
    __syncthreads();

    int warp = tid >> 5, lane = tid & 31;
    int t = blockIdx.x * 8 + warp;
    const float* xr = x + (size_t)t * DM;
    float acc[NE];
#pragma unroll
    for (int e = 0; e < NE; e++) acc[e] = 0.f;
    for (int d = lane; d < DM; d += 32) {
        float xv = xr[d];
        const float* g = &sgw[d * 9];
#pragma unroll
        for (int e = 0; e < NE; e++) acc[e] += xv * g[e];
    }
#pragma unroll
    for (int e = 0; e < NE; e++) {
#pragma unroll
        for (int off = 16; off; off >>= 1)
            acc[e] += __shfl_xor_sync(0xffffffffu, acc[e], off);
    }
    if (lane == 0) {
        float l[NE];
#pragma unroll
        for (int e = 0; e < NE; e++) l[e] = acc[e] + gb[e];
        int i0 = 0;
#pragma unroll
        for (int e = 1; e < NE; e++) if (l[e] > l[i0]) i0 = e;
        int i1 = (i0 == 0) ? 1 : 0;
#pragma unroll
        for (int e = 0; e < NE; e++) if (e != i0 && l[e] > l[i1]) i1 = e;
        float p1 = expf(l[i1] - l[i0]);
        float w0 = 1.f / (1.f + p1);
        g_topk_i[2 * t] = i0; g_topk_i[2 * t + 1] = i1;
        g_topk_w[2 * t] = w0; g_topk_w[2 * t + 1] = 1.f - w0;
    }
}

// ---------------- routing (parallel, order-preserving) ----------------
// A: per 256-token chunk, per expert: local inclusive ranks + chunk totals
__global__ __launch_bounds__(256) void routeA_kernel() {
    __shared__ int wsum[8];
    int tid = threadIdx.x, lane = tid & 31, warp = tid >> 5;
    int t = blockIdx.x * 256 + tid;
    int i0 = g_topk_i[2 * t], i1 = g_topk_i[2 * t + 1];
    int lr0 = 0, lr1 = 0;
    for (int e = 0; e < NE; e++) {
        int v = (i0 == e || i1 == e) ? 1 : 0;
#pragma unroll
        for (int off = 1; off < 32; off <<= 1) {
            int u = __shfl_up_sync(0xffffffffu, v, off);
            if (lane >= off) v += u;
        }
        if (lane == 31) wsum[warp] = v;
        __syncthreads();
        int woff = 0, total = 0;
#pragma unroll
        for (int w = 0; w < 8; w++) { int s = wsum[w]; total += s; if (w < warp) woff += s; }
        int lr = woff + v;
        if (i0 == e) lr0 = lr;
        if (i1 == e) lr1 = lr;
        if (tid == 0) g_ccnt[blockIdx.x * NE + e] = total;
        __syncthreads();
    }
    g_lrank[2 * t] = lr0; g_lrank[2 * t + 1] = lr1;
}

// B: exclusive prefix over chunks (8 threads, serial over 32 chunks)
__global__ __launch_bounds__(32) void routeB_kernel() {
    int e = threadIdx.x;
    if (e < NE) {
        int off = 0;
        for (int b = 0; b < NCHUNK; b++) {
            g_coff[b * NE + e] = off;
            off += g_ccnt[b * NE + e];
        }
        g_cnt[e] = min(off, CAP);
    }
}

// C: global rank = chunk offset + local rank -> slots + scatter index
__global__ __launch_bounds__(256) void routeC_kernel() {
    int tid = threadIdx.x;
    int t = blockIdx.x * 256 + tid;
#pragma unroll
    for (int j = 0; j < 2; j++) {
        int e = g_topk_i[2 * t + j];
        int rank = g_coff[blockIdx.x * NE + e] + g_lrank[2 * t + j];
        int s = (rank <= CAP) ? rank - 1 : -1;
        g_slot[2 * t + j] = s;
        if (s >= 0) g_idx[e * CAP + s] = t;
    }
}

// ---------------- expert GEMM: fp16 mma.sync m16n8k16 + ldmatrix + 3-stage cp.async ----------------
template<bool GATHER, bool RELU, int KDIM, int NDIM>
__global__ __launch_bounds__(256, 2)
void gemm_kernel(const __half* __restrict__ Aglob,
                 const __half* __restrict__ Wglob,
                 const float* __restrict__ biasGlob) {
    extern __shared__ char smem[];
    __shared__ int sTok[BM];

    const int e = blockIdx.z;
    const int rowBase = blockIdx.y * BM;
    const int nBase = blockIdx.x * BN;
    const int tid = threadIdx.x;

    const __half* Abase = GATHER ? Aglob : (g_h + (size_t)e * CAP * KDIM);
    const __half* W = Wglob + ((size_t)e * NDIM + nBase) * KDIM;
    const float* bias = biasGlob + e * NDIM;

    if (tid < BM) {
        int r = rowBase + tid;
        sTok[tid] = GATHER ? ((r < g_cnt[e]) ? g_idx[e * CAP + r] : -1) : (rowBase + tid);
    }
    __syncthreads();

    const unsigned smem_base = (unsigned)__cvta_generic_to_shared(smem);

    const int ldRow0 = tid >> 2;
    const int ldC0 = tid & 3;

    auto load_stage = [&](int slot, int kk) {    // kk in halves
        unsigned aB = smem_base + slot * STAGE_BYTES;
        unsigned bB = aB + A_STAGE_BYTES;
#pragma unroll
        for (int i = 0; i < 2; i++) {
            int row = ldRow0 + i * 64;
            int r7 = row & 7;
            int tok = sTok[row];
            const __half* asrc = Abase + (size_t)((tok < 0) ? 0 : tok) * KDIM + kk;
            const __half* bsrc = W + (size_t)row * KDIM + kk;
#pragma unroll
            for (int j = 0; j < 2; j++) {
                int c = ldC0 + j * 4;
                unsigned sw = (unsigned)(row * 128 + ((c ^ r7) << 4));
                cp_async16(aB + sw, asrc + c * 8, (tok >= 0) ? 16 : 0);
                cp_async16(bB + sw, bsrc + c * 8, 16);
            }
        }
    };

    float acc[4][4][4];
#pragma unroll
    for (int mt = 0; mt < 4; mt++)
#pragma unroll
        for (int nt = 0; nt < 4; nt++)
#pragma unroll
            for (int i = 0; i < 4; i++) acc[mt][nt][i] = 0.f;

    const int warp = tid >> 5, lane = tid & 31;
    const int wm = warp >> 2, wn = warp & 3;       // 2x4 grid, warp tile 64x32
    const int t4 = lane >> 3;
    const int row7 = lane & 7;

    const int aRowByte = (wm * 64 + (t4 & 1) * 8 + row7) * 128;
    const int aG = (t4 >> 1);
    const int bRowByte = (wn * 32 + (t4 >> 1) * 8 + row7) * 128;
    const int bG = (t4 & 1);

    const int NIT = KDIM / BKH;

    load_stage(0, 0); cp_commit();
    load_stage(1, BKH); cp_commit();

    int slot = 0, nslot = 2;
    for (int k = 0; k < NIT; k++) {
        cp_wait1();
        __syncthreads();

        int nk = k + 2;
        if (nk < NIT) load_stage(nslot, nk * BKH);
        cp_commit();

        const unsigned sA = smem_base + slot * STAGE_BYTES;
        const unsigned sB = sA + A_STAGE_BYTES;

#pragma unroll
        for (int gr = 0; gr < 4; gr++) {           // k16 groups within BKH=64
            unsigned a[4][4], b[4][2];
#pragma unroll
            for (int mt = 0; mt < 4; mt++)
                ldsm_x4(a[mt], sA + aRowByte + mt * 2048 + ((((2 * gr) + aG) ^ row7) << 4));
#pragma unroll
            for (int ntp = 0; ntp < 2; ntp++) {
                unsigned r[4];
                ldsm_x4(r, sB + bRowByte + ntp * 2048 + ((((2 * gr) + bG) ^ row7) << 4));
                b[2 * ntp][0] = r[0]; b[2 * ntp][1] = r[1];
                b[2 * ntp + 1][0] = r[2]; b[2 * ntp + 1][1] = r[3];
            }
#pragma unroll
            for (int mt = 0; mt < 4; mt++)
#pragma unroll
                for (int nt = 0; nt < 4; nt++)
                    mma_f16(acc[mt][nt], a[mt], b[nt]);
        }
        slot = (slot == NSTG - 1) ? 0 : slot + 1;
        nslot = (nslot == NSTG - 1) ? 0 : nslot + 1;
    }

    // epilogue
    const int gid = lane >> 2, tig = lane & 3;
#pragma unroll
    for (int mt = 0; mt < 4; mt++) {
        int r0 = rowBase + wm * 64 + mt * 16 + gid;
#pragma unroll
        for (int nt = 0; nt < 4; nt++) {
            int c = nBase + wn * 32 + nt * 8 + 2 * tig;
            float bv0 = bias[c], bv1 = bias[c + 1];
            float v00 = acc[mt][nt][0] + bv0;
            float v01 = acc[mt][nt][1] + bv1;
            float v10 = acc[mt][nt][2] + bv0;
            float v11 = acc[mt][nt][3] + bv1;
            if (RELU) {
                __half* OutH = g_h + (size_t)e * CAP * NDIM;
                *reinterpret_cast<__half2*>(OutH + (size_t)r0 * NDIM + c) =
                    __floats2half2_rn(fmaxf(v00, 0.f), fmaxf(v01, 0.f));
                *reinterpret_cast<__half2*>(OutH + (size_t)(r0 + 8) * NDIM + c) =
                    __floats2half2_rn(fmaxf(v10, 0.f), fmaxf(v11, 0.f));
            } else {
                float* OutF = g_oute + (size_t)e * CAP * NDIM;
                *reinterpret_cast<float2*>(OutF + (size_t)r0 * NDIM + c) = make_float2(v00, v01);
                *reinterpret_cast<float2*>(OutF + (size_t)(r0 + 8) * NDIM + c) = make_float2(v10, v11);
            }
        }
    }
}

// ---------------- combine ----------------
__global__ __launch_bounds__(256) void combine_kernel(float* __restrict__ out) {
    int t = blockIdx.x;
    int i0 = g_topk_i[2 * t], i1 = g_topk_i[2 * t + 1];
    int s0 = g_slot[2 * t], s1 = g_slot[2 * t + 1];
    float w0 = g_topk_w[2 * t], w1v = g_topk_w[2 * t + 1];
    int d = threadIdx.x * 4;
    float4 a = make_float4(0.f, 0.f, 0.f, 0.f);
    if (s0 >= 0) {
        float4 v = *reinterpret_cast<const float4*>(g_oute + ((size_t)i0 * CAP + s0) * DM + d);
        a.x += w0 * v.x; a.y += w0 * v.y; a.z += w0 * v.z; a.w += w0 * v.w;
    }
    if (s1 >= 0) {
        float4 v = *reinterpret_cast<const float4*>(g_oute + ((size_t)i1 * CAP + s1) * DM + d);
        a.x += w1v * v.x; a.y += w1v * v.y; a.z += w1v * v.z; a.w += w1v * v.w;
    }
    *reinterpret_cast<float4*>(out + (size_t)t * DM + d) = a;
}

// ---------------- launch ----------------
extern "C" void kernel_launch(void* const* d_in, const int* in_sizes, int n_in,
                              void* d_out, int out_size) {
    (void)in_sizes; (void)n_in; (void)out_size;
    const float* x      = (const float*)d_in[0];
    const float* gate_w = (const float*)d_in[1];
    const float* gate_b = (const float*)d_in[2];
    const float* w1     = (const float*)d_in[3];
    const float* b1     = (const float*)d_in[4];
    const float* w2     = (const float*)d_in[5];
    const float* b2     = (const float*)d_in[6];
    float* out = (float*)d_out;

    static bool attr_done = false;
    if (!attr_done) {
        cudaFuncSetAttribute(gemm_kernel<true,  true,  DM,    FFDIM>,
                             cudaFuncAttributeMaxDynamicSharedMemorySize, SMEM_BYTES);
        cudaFuncSetAttribute(gemm_kernel<false, false, FFDIM, DM>,
                             cudaFuncAttributeMaxDynamicSharedMemorySize, SMEM_BYTES);
        attr_done = true;
    }

    static __half *p_xh = nullptr, *p_w1h = nullptr, *p_w2h = nullptr;
    if (!p_xh) {
        cudaGetSymbolAddress((void**)&p_xh,  g_xh);
        cudaGetSymbolAddress((void**)&p_w1h, g_w1h);
        cudaGetSymbolAddress((void**)&p_w2h, g_w2h);
    }

    xh_kernel<<<2048, 256>>>((const float4*)x, (__half2*)p_xh, S_TOK * DM / 4);
    wtr_kernel<true ><<<dim3(FFDIM / 32, DM / 64, NE), 256>>>(w1);
    wtr_kernel<false><<<dim3(DM / 32, FFDIM / 64, NE), 256>>>(w2);

    gate_kernel<<<S_TOK / 8, 256>>>(x, gate_w, gate_b);
    routeA_kernel<<<NCHUNK, 256>>>();
    routeB_kernel<<<1, 32>>>();
    routeC_kernel<<<NCHUNK, 256>>>();

    gemm_kernel<true,  true,  DM,    FFDIM>
        <<<dim3(FFDIM / BN, CAP / BM, NE), 256, SMEM_BYTES>>>(p_xh, p_w1h, b1);
    gemm_kernel<false, false, FFDIM, DM>
        <<<dim3(DM / BN,    CAP / BM, NE), 256, SMEM_BYTES>>>(nullptr, p_w2h, b2);
    combine_kernel<<<S_TOK, 256>>>(out);
}

// round 10
// speedup vs baseline: 2.9223x; 1.0342x over previous
#include <cuda_runtime.h>
#include <cuda_fp16.h>
#include <math.h>

#define S_TOK 8192
#define DM    1024
#define FFDIM 4096
#define NE    8
#define CAP   1280
#define NCHUNK 32                              // routing chunks of 256 tokens

#define BM 128
#define BN 128
#define BKH 64                                 // K halves per stage (128B row)
#define NSTG 3
#define A_STAGE_BYTES (BM * 128)               // 16384
#define STAGE_BYTES   (2 * A_STAGE_BYTES)      // 32768
#define SMEM_BYTES    (NSTG * STAGE_BYTES)     // 98304

// ---------------- scratch (device globals; no allocation allowed) ----------------
__device__ int    g_topk_i[S_TOK * 2];
__device__ float  g_topk_w[S_TOK * 2];
__device__ int    g_slot[S_TOK * 2];
__device__ int    g_lrank[S_TOK * 2];
__device__ int    g_ccnt[NCHUNK * NE];
__device__ int    g_coff[NCHUNK * NE];
__device__ int    g_idx[NE * CAP];
__device__ int    g_cnt[NE];
__device__ __half g_xh [(size_t)S_TOK * DM];        // fp16 x (token order, K-major)
__device__ __half g_w1h[(size_t)NE * FFDIM * DM];   // w1 -> [e][FF][DM] K-major fp16
__device__ __half g_w2h[(size_t)NE * DM * FFDIM];   // w2 -> [e][DM][FF] K-major fp16
__device__ __half g_h  [(size_t)NE * CAP * FFDIM];  // hidden fp16 (K-major for GEMM2)
__device__ float  g_oute [(size_t)NE * CAP * DM];   // expert outputs, split-K half 0 (+bias)
__device__ float  g_oute2[(size_t)NE * CAP * DM];   // expert outputs, split-K half 1

__device__ __forceinline__ void mma_f16(float* d, const unsigned* a, const unsigned* b) {
    asm volatile(
        "mma.sync.aligned.m16n8k16.row.col.f32.f16.f16.f32 "
        "{%0,%1,%2,%3}, {%4,%5,%6,%7}, {%8,%9}, {%0,%1,%2,%3};\n"
        : "+f"(d[0]), "+f"(d[1]), "+f"(d[2]), "+f"(d[3])
        : "r"(a[0]), "r"(a[1]), "r"(a[2]), "r"(a[3]), "r"(b[0]), "r"(b[1]));
}

__device__ __forceinline__ void ldsm_x4(unsigned* r, unsigned addr) {
    asm volatile("ldmatrix.sync.aligned.m8n8.x4.shared.b16 {%0,%1,%2,%3}, [%4];"
                 : "=r"(r[0]), "=r"(r[1]), "=r"(r[2]), "=r"(r[3]) : "r"(addr));
}

__device__ __forceinline__ void cp_async16(unsigned smem_addr, const void* gptr, int src_bytes) {
    asm volatile("cp.async.ca.shared.global [%0], [%1], 16, %2;\n"
                 :: "r"(smem_addr), "l"(gptr), "r"(src_bytes));
}
__device__ __forceinline__ void cp_commit() { asm volatile("cp.async.commit_group;\n"); }
__device__ __forceinline__ void cp_wait1()  { asm volatile("cp.async.wait_group 1;\n"); }

// ---------------- convert x -> fp16 ----------------
__global__ __launch_bounds__(256) void xh_kernel(const float4* __restrict__ src,
                                                 __half2* __restrict__ dst, int n4) {
    int i = blockIdx.x * 256 + threadIdx.x;
    int stride = gridDim.x * 256;
    for (; i < n4; i += stride) {
        float4 v = src[i];
        dst[2 * i]     = __floats2half2_rn(v.x, v.y);
        dst[2 * i + 1] = __floats2half2_rn(v.z, v.w);
    }
}

// ---------------- transpose + convert weights: src[e][R][C] -> dst[e][C][R] fp16 ----------------
template<bool W1>
__global__ __launch_bounds__(256) void wtr_kernel(const float* __restrict__ src) {
    constexpr int R = W1 ? DM : FFDIM;
    constexpr int C = W1 ? FFDIM : DM;
    __half* dst = W1 ? g_w1h : g_w2h;
    __shared__ float b[32][65];                 // b[c][r]
    int e = blockIdx.z;
    int c0 = blockIdx.x * 32, r0 = blockIdx.y * 64;
    const float* s = src + (size_t)e * R * C;
    __half* d = dst + (size_t)e * R * C;
    int lane = threadIdx.x & 31, w = threadIdx.x >> 5;
#pragma unroll
    for (int i = 0; i < 8; i++) {
        int r = w * 8 + i;
        b[lane][r] = s[(size_t)(r0 + r) * C + c0 + lane];
    }
    __syncthreads();
#pragma unroll
    for (int i = 0; i < 4; i++) {
        int c = w + 8 * i;
        __half2 h = __floats2half2_rn(b[c][2 * lane], b[c][2 * lane + 1]);
        *reinterpret_cast<__half2*>(d + (size_t)(c0 + c) * R + r0 + 2 * lane) = h;
    }
}

// ---------------- gating (float4 loads for MLP) ----------------
__global__ __launch_bounds__(256) void gate_kernel(const float* __restrict__ x,
                                                   const float* __restrict__ gw,
                                                   const float* __restrict__ gb) {
    __shared__ float sgw[DM * 9];
    int tid = threadIdx.x;
    for (int i = tid; i < DM * NE; i += 256) sgw[(i >> 3) * 9 + (i & 7)] = gw[i];
    __syncthreads();

    int warp = tid >> 5, lane = tid & 31;
    int t = blockIdx.x * 8 + warp;
    const float* xr = x + (size_t)t * DM;
    float acc[NE];
#pragma unroll
    for (int e = 0; e < NE; e++) acc[e] = 0.f;
#pragma unroll
    for (int d0 = 0; d0 < DM; d0 += 128) {
        int d = d0 + lane * 4;
        float4 xv = *reinterpret_cast<const float4*>(xr + d);
        const float* g0 = &sgw[d * 9];
#pragma unroll
        for (int e = 0; e < NE; e++)
            acc[e] += xv.x * g0[e] + xv.y * g0[9 + e] + xv.z * g0[18 + e] + xv.w * g0[27 + e];
    }
#pragma unroll
    for (int e = 0; e < NE; e++) {
#pragma unroll
        for (int off = 16; off; off >>= 1)
            acc[e] += __shfl_xor_sync(0xffffffffu, acc[e], off);
    }
    if (lane == 0) {
        float l[NE];
#pragma unroll
        for (int e = 0; e < NE; e++) l[e] = acc[e] + gb[e];
        int i0 = 0;
#pragma unroll
        for (int e = 1; e < NE; e++) if (l[e] > l[i0]) i0 = e;
        int i1 = (i0 == 0) ? 1 : 0;
#pragma unroll
        for (int e = 0; e < NE; e++) if (e != i0 && l[e] > l[i1]) i1 = e;
        float p1 = expf(l[i1] - l[i0]);
        float w0 = 1.f / (1.f + p1);
        g_topk_i[2 * t] = i0; g_topk_i[2 * t + 1] = i1;
        g_topk_w[2 * t] = w0; g_topk_w[2 * t + 1] = 1.f - w0;
    }
}

// ---------------- routing (parallel, order-preserving) ----------------
__global__ __launch_bounds__(256) void routeA_kernel() {
    __shared__ int wsum[8];
    int tid = threadIdx.x, lane = tid & 31, warp = tid >> 5;
    int t = blockIdx.x * 256 + tid;
    int i0 = g_topk_i[2 * t], i1 = g_topk_i[2 * t + 1];
    int lr0 = 0, lr1 = 0;
    for (int e = 0; e < NE; e++) {
        int v = (i0 == e || i1 == e) ? 1 : 0;
#pragma unroll
        for (int off = 1; off < 32; off <<= 1) {
            int u = __shfl_up_sync(0xffffffffu, v, off);
            if (lane >= off) v += u;
        }
        if (lane == 31) wsum[warp] = v;
        __syncthreads();
        int woff = 0, total = 0;
#pragma unroll
        for (int w = 0; w < 8; w++) { int s = wsum[w]; total += s; if (w < warp) woff += s; }
        int lr = woff + v;
        if (i0 == e) lr0 = lr;
        if (i1 == e) lr1 = lr;
        if (tid == 0) g_ccnt[blockIdx.x * NE + e] = total;
        __syncthreads();
    }
    g_lrank[2 * t] = lr0; g_lrank[2 * t + 1] = lr1;
}

__global__ __launch_bounds__(32) void routeB_kernel() {
    int e = threadIdx.x;
    if (e < NE) {
        int off = 0;
        for (int b = 0; b < NCHUNK; b++) {
            g_coff[b * NE + e] = off;
            off += g_ccnt[b * NE + e];
        }
        g_cnt[e] = min(off, CAP);
    }
}

__global__ __launch_bounds__(256) void routeC_kernel() {
    int tid = threadIdx.x;
    int t = blockIdx.x * 256 + tid;
#pragma unroll
    for (int j = 0; j < 2; j++) {
        int e = g_topk_i[2 * t + j];
        int rank = g_coff[blockIdx.x * NE + e] + g_lrank[2 * t + j];
        int s = (rank <= CAP) ? rank - 1 : -1;
        g_slot[2 * t + j] = s;
        if (s >= 0) g_idx[e * CAP + s] = t;
    }
}

// ---------------- expert GEMM: fp16 mma.sync m16n8k16 + ldmatrix + 3-stage cp.async ----------------
// SPLITK>1: blockIdx.z = e*SPLITK + half; each half covers KDIM/SPLITK, half1 -> g_oute2, no bias.
template<bool GATHER, bool RELU, int KDIM, int NDIM, int SPLITK>
__global__ __launch_bounds__(256, 2)
void gemm_kernel(const __half* __restrict__ Aglob,
                 const __half* __restrict__ Wglob,
                 const float* __restrict__ biasGlob) {
    extern __shared__ char smem[];
    __shared__ int sTok[BM];

    const int e = blockIdx.z / SPLITK;
    const int hlf = blockIdx.z % SPLITK;
    const int kOff = hlf * (KDIM / SPLITK);       // in halves
    const int rowBase = blockIdx.y * BM;
    const int nBase = blockIdx.x * BN;
    const int tid = threadIdx.x;

    const __half* Abase = GATHER ? Aglob : (g_h + (size_t)e * CAP * KDIM);
    const __half* W = Wglob + ((size_t)e * NDIM + nBase) * KDIM;
    const float* bias = biasGlob + e * NDIM;

    if (tid < BM) {
        int r = rowBase + tid;
        sTok[tid] = GATHER ? ((r < g_cnt[e]) ? g_idx[e * CAP + r] : -1) : (rowBase + tid);
    }
    __syncthreads();

    const unsigned smem_base = (unsigned)__cvta_generic_to_shared(smem);

    const int ldRow0 = tid >> 2;
    const int ldC0 = tid & 3;

    auto load_stage = [&](int slot, int kk) {    // kk in halves (absolute)
        unsigned aB = smem_base + slot * STAGE_BYTES;
        unsigned bB = aB + A_STAGE_BYTES;
#pragma unroll
        for (int i = 0; i < 2; i++) {
            int row = ldRow0 + i * 64;
            int r7 = row & 7;
            int tok = sTok[row];
            const __half* asrc = Abase + (size_t)((tok < 0) ? 0 : tok) * KDIM + kk;
            const __half* bsrc = W + (size_t)row * KDIM + kk;
#pragma unroll
            for (int j = 0; j < 2; j++) {
                int c = ldC0 + j * 4;
                unsigned sw = (unsigned)(row * 128 + ((c ^ r7) << 4));
                cp_async16(aB + sw, asrc + c * 8, (tok >= 0) ? 16 : 0);
                cp_async16(bB + sw, bsrc + c * 8, 16);
            }
        }
    };

    float acc[4][4][4];
#pragma unroll
    for (int mt = 0; mt < 4; mt++)
#pragma unroll
        for (int nt = 0; nt < 4; nt++)
#pragma unroll
            for (int i = 0; i < 4; i++) acc[mt][nt][i] = 0.f;

    const int warp = tid >> 5, lane = tid & 31;
    const int wm = warp >> 2, wn = warp & 3;
    const int t4 = lane >> 3;
    const int row7 = lane & 7;

    const int aRowByte = (wm * 64 + (t4 & 1) * 8 + row7) * 128;
    const int aG = (t4 >> 1);
    const int bRowByte = (wn * 32 + (t4 >> 1) * 8 + row7) * 128;
    const int bG = (t4 & 1);

    const int NIT = (KDIM / SPLITK) / BKH;

    load_stage(0, kOff); cp_commit();
    load_stage(1, kOff + BKH); cp_commit();

    int slot = 0, nslot = 2;
    for (int k = 0; k < NIT; k++) {
        cp_wait1();
        __syncthreads();

        int nk = k + 2;
        if (nk < NIT) load_stage(nslot, kOff + nk * BKH);
        cp_commit();

        const unsigned sA = smem_base + slot * STAGE_BYTES;
        const unsigned sB = sA + A_STAGE_BYTES;

#pragma unroll
        for (int gr = 0; gr < 4; gr++) {
            unsigned a[4][4], b[4][2];
#pragma unroll
            for (int mt = 0; mt < 4; mt++)
                ldsm_x4(a[mt], sA + aRowByte + mt * 2048 + ((((2 * gr) + aG) ^ row7) << 4));
#pragma unroll
            for (int ntp = 0; ntp < 2; ntp++) {
                unsigned r[4];
                ldsm_x4(r, sB + bRowByte + ntp * 2048 + ((((2 * gr) + bG) ^ row7) << 4));
                b[2 * ntp][0] = r[0]; b[2 * ntp][1] = r[1];
                b[2 * ntp + 1][0] = r[2]; b[2 * ntp + 1][1] = r[3];
            }
#pragma unroll
            for (int mt = 0; mt < 4; mt++)
#pragma unroll
                for (int nt = 0; nt < 4; nt++)
                    mma_f16(acc[mt][nt], a[mt], b[nt]);
        }
        slot = (slot == NSTG - 1) ? 0 : slot + 1;
        nslot = (nslot == NSTG - 1) ? 0 : nslot + 1;
    }

    // epilogue
    const int gid = lane >> 2, tig = lane & 3;
#pragma unroll
    for (int mt = 0; mt < 4; mt++) {
        int r0 = rowBase + wm * 64 + mt * 16 + gid;
#pragma unroll
        for (int nt = 0; nt < 4; nt++) {
            int c = nBase + wn * 32 + nt * 8 + 2 * tig;
            float bv0 = (hlf == 0) ? bias[c] : 0.f;
            float bv1 = (hlf == 0) ? bias[c + 1] : 0.f;
            float v00 = acc[mt][nt][0] + bv0;
            float v01 = acc[mt][nt][1] + bv1;
            float v10 = acc[mt][nt][2] + bv0;
            float v11 = acc[mt][nt][3] + bv1;
            if (RELU) {
                __half* OutH = g_h + (size_t)e * CAP * NDIM;
                *reinterpret_cast<__half2*>(OutH + (size_t)r0 * NDIM + c) =
                    __floats2half2_rn(fmaxf(v00, 0.f), fmaxf(v01, 0.f));
                *reinterpret_cast<__half2*>(OutH + (size_t)(r0 + 8) * NDIM + c) =
                    __floats2half2_rn(fmaxf(v10, 0.f), fmaxf(v11, 0.f));
            } else {
                float* OutF = ((hlf == 0) ? g_oute : g_oute2) + (size_t)e * CAP * NDIM;
                *reinterpret_cast<float2*>(OutF + (size_t)r0 * NDIM + c) = make_float2(v00, v01);
                *reinterpret_cast<float2*>(OutF + (size_t)(r0 + 8) * NDIM + c) = make_float2(v10, v11);
            }
        }
    }
}

// ---------------- combine (sums split-K halves) ----------------
__global__ __launch_bounds__(256) void combine_kernel(float* __restrict__ out) {
    int t = blockIdx.x;
    int i0 = g_topk_i[2 * t], i1 = g_topk_i[2 * t + 1];
    int s0 = g_slot[2 * t], s1 = g_slot[2 * t + 1];
    float w0 = g_topk_w[2 * t], w1v = g_topk_w[2 * t + 1];
    int d = threadIdx.x * 4;
    float4 a = make_float4(0.f, 0.f, 0.f, 0.f);
    if (s0 >= 0) {
        size_t off = ((size_t)i0 * CAP + s0) * DM + d;
        float4 v = *reinterpret_cast<const float4*>(g_oute + off);
        float4 u = *reinterpret_cast<const float4*>(g_oute2 + off);
        a.x += w0 * (v.x + u.x); a.y += w0 * (v.y + u.y);
        a.z += w0 * (v.z + u.z); a.w += w0 * (v.w + u.w);
    }
    if (s1 >= 0) {
        size_t off = ((size_t)i1 * CAP + s1) * DM + d;
        float4 v = *reinterpret_cast<const float4*>(g_oute + off);
        float4 u = *reinterpret_cast<const float4*>(g_oute2 + off);
        a.x += w1v * (v.x + u.x); a.y += w1v * (v.y + u.y);
        a.z += w1v * (v.z + u.z); a.w += w1v * (v.w + u.w);
    }
    *reinterpret_cast<float4*>(out + (size_t)t * DM + d) = a;
}

// ---------------- launch ----------------
extern "C" void kernel_launch(void* const* d_in, const int* in_sizes, int n_in,
                              void* d_out, int out_size) {
    (void)in_sizes; (void)n_in; (void)out_size;
    const float* x      = (const float*)d_in[0];
    const float* gate_w = (const float*)d_in[1];
    const float* gate_b = (const float*)d_in[2];
    const float* w1     = (const float*)d_in[3];
    const float* b1     = (const float*)d_in[4];
    const float* w2     = (const float*)d_in[5];
    const float* b2     = (const float*)d_in[6];
    float* out = (float*)d_out;

    static bool attr_done = false;
    if (!attr_done) {
        cudaFuncSetAttribute(gemm_kernel<true,  true,  DM,    FFDIM, 1>,
                             cudaFuncAttributeMaxDynamicSharedMemorySize, SMEM_BYTES);
        cudaFuncSetAttribute(gemm_kernel<false, false, FFDIM, DM,    2>,
                             cudaFuncAttributeMaxDynamicSharedMemorySize, SMEM_BYTES);
        attr_done = true;
    }

    static __half *p_xh = nullptr, *p_w1h = nullptr, *p_w2h = nullptr;
    if (!p_xh) {
        cudaGetSymbolAddress((void**)&p_xh,  g_xh);
        cudaGetSymbolAddress((void**)&p_w1h, g_w1h);
        cudaGetSymbolAddress((void**)&p_w2h, g_w2h);
    }

    xh_kernel<<<2048, 256>>>((const float4*)x, (__half2*)p_xh, S_TOK * DM / 4);
    wtr_kernel<true ><<<dim3(FFDIM / 32, DM / 64, NE), 256>>>(w1);
    wtr_kernel<false><<<dim3(DM / 32, FFDIM / 64, NE), 256>>>(w2);

    gate_kernel<<<S_TOK / 8, 256>>>(x, gate_w, gate_b);
    routeA_kernel<<<NCHUNK, 256>>>();
    routeB_kernel<<<1, 32>>>();
    routeC_kernel<<<NCHUNK, 256>>>();

    gemm_kernel<true,  true,  DM,    FFDIM, 1>
        <<<dim3(FFDIM / BN, CAP / BM, NE), 256, SMEM_BYTES>>>(p_xh, p_w1h, b1);
    gemm_kernel<false, false, FFDIM, DM,    2>
        <<<dim3(DM / BN,    CAP / BM, NE * 2), 256, SMEM_BYTES>>>(nullptr, p_w2h, b2);
    combine_kernel<<<S_TOK, 256>>>(out);
}

// round 11
// speedup vs baseline: 3.4628x; 1.1850x over previous
#include <cuda_runtime.h>
#include <cuda_fp16.h>
#include <math.h>

#define S_TOK 8192
#define DM    1024
#define FFDIM 4096
#define NE    8
#define CAP   1280
#define NCHUNK 32                              // routing chunks of 256 tokens

#define BM 128
#define BN 128
#define BKH 64                                 // K halves per stage (128B row)
#define NSTG 3
#define A_STAGE_BYTES (BM * 128)               // 16384
#define STAGE_BYTES   (2 * A_STAGE_BYTES)      // 32768
#define SMEM_BYTES    (NSTG * STAGE_BYTES)     // 98304

// ---------------- scratch (device globals; no allocation allowed) ----------------
__device__ int    g_topk_i[S_TOK * 2];
__device__ float  g_topk_w[S_TOK * 2];
__device__ int    g_slot[S_TOK * 2];
__device__ int    g_lrank[S_TOK * 2];
__device__ int    g_ccnt[NCHUNK * NE];
__device__ int    g_coff[NCHUNK * NE];
__device__ int    g_idx[NE * CAP];
__device__ int    g_cnt[NE];
__device__ __half g_xh [(size_t)S_TOK * DM];        // fp16 x (token order, K-major)
__device__ __half g_w1h[(size_t)NE * FFDIM * DM];   // w1 -> [e][FF][DM] K-major fp16
__device__ __half g_w2h[(size_t)NE * DM * FFDIM];   // w2 -> [e][DM][FF] K-major fp16
__device__ __half g_h  [(size_t)NE * CAP * FFDIM];  // hidden fp16 (K-major for GEMM2)
__device__ float  g_oute [(size_t)NE * CAP * DM];   // expert outputs, split-K half 0 (+bias)
__device__ float  g_oute2[(size_t)NE * CAP * DM];   // expert outputs, split-K half 1

__device__ __forceinline__ void mma_f16(float* d, const unsigned* a, const unsigned* b) {
    asm volatile(
        "mma.sync.aligned.m16n8k16.row.col.f32.f16.f16.f32 "
        "{%0,%1,%2,%3}, {%4,%5,%6,%7}, {%8,%9}, {%0,%1,%2,%3};\n"
        : "+f"(d[0]), "+f"(d[1]), "+f"(d[2]), "+f"(d[3])
        : "r"(a[0]), "r"(a[1]), "r"(a[2]), "r"(a[3]), "r"(b[0]), "r"(b[1]));
}

__device__ __forceinline__ void ldsm_x4(unsigned* r, unsigned addr) {
    asm volatile("ldmatrix.sync.aligned.m8n8.x4.shared.b16 {%0,%1,%2,%3}, [%4];"
                 : "=r"(r[0]), "=r"(r[1]), "=r"(r[2]), "=r"(r[3]) : "r"(addr));
}

// streaming 16B copy, L2-only (.cg): operand tiles never re-read through L1
__device__ __forceinline__ void cp_async16(unsigned smem_addr, const void* gptr, int src_bytes) {
    asm volatile("cp.async.cg.shared.global [%0], [%1], 16, %2;\n"
                 :: "r"(smem_addr), "l"(gptr), "r"(src_bytes));
}
__device__ __forceinline__ void cp_commit() { asm volatile("cp.async.commit_group;\n"); }
__device__ __forceinline__ void cp_wait1()  { asm volatile("cp.async.wait_group 1;\n"); }

// ---------------- fused: x -> fp16 conversion + gate logits + top2 ----------------
// 8 warps/block, warp = one token. Gate weights transposed in smem: sgwt[e][d],
// so each lane's per-expert read is 4 consecutive floats (conflict-free float4 LDS).
__global__ __launch_bounds__(256) void gatex_kernel(const float* __restrict__ x,
                                                    const float* __restrict__ gw,
                                                    const float* __restrict__ gb) {
    __shared__ float sgwt[NE * DM];
    int tid = threadIdx.x;
    for (int i = tid; i < DM * NE; i += 256) {
        int d = i >> 3, e = i & 7;
        sgwt[e * DM + d] = gw[i];
    }
    __syncthreads();

    int warp = tid >> 5, lane = tid & 31;
    int t = blockIdx.x * 8 + warp;
    const float* xr = x + (size_t)t * DM;
    __half2* xo = reinterpret_cast<__half2*>(g_xh + (size_t)t * DM);

    float acc[NE];
#pragma unroll
    for (int e = 0; e < NE; e++) acc[e] = 0.f;
#pragma unroll
    for (int d0 = 0; d0 < DM; d0 += 128) {
        int d = d0 + lane * 4;
        float4 xv = *reinterpret_cast<const float4*>(xr + d);
        xo[d >> 1]       = __floats2half2_rn(xv.x, xv.y);
        xo[(d >> 1) + 1] = __floats2half2_rn(xv.z, xv.w);
#pragma unroll
        for (int e = 0; e < NE; e++) {
            float4 gv = *reinterpret_cast<const float4*>(&sgwt[e * DM + d]);
            acc[e] += xv.x * gv.x + xv.y * gv.y + xv.z * gv.z + xv.w * gv.w;
        }
    }
#pragma unroll
    for (int e = 0; e < NE; e++) {
#pragma unroll
        for (int off = 16; off; off >>= 1)
            acc[e] += __shfl_xor_sync(0xffffffffu, acc[e], off);
    }
    if (lane == 0) {
        float l[NE];
#pragma unroll
        for (int e = 0; e < NE; e++) l[e] = acc[e] + gb[e];
        int i0 = 0;
#pragma unroll
        for (int e = 1; e < NE; e++) if (l[e] > l[i0]) i0 = e;
        int i1 = (i0 == 0) ? 1 : 0;
#pragma unroll
        for (int e = 0; e < NE; e++) if (e != i0 && l[e] > l[i1]) i1 = e;
        float p1 = expf(l[i1] - l[i0]);
        float w0 = 1.f / (1.f + p1);
        g_topk_i[2 * t] = i0; g_topk_i[2 * t + 1] = i1;
        g_topk_w[2 * t] = w0; g_topk_w[2 * t + 1] = 1.f - w0;
    }
}

// ---------------- transpose + convert weights: src[e][R][C] -> dst[e][C][R] fp16 ----------------
template<bool W1>
__global__ __launch_bounds__(256) void wtr_kernel(const float* __restrict__ src) {
    constexpr int R = W1 ? DM : FFDIM;
    constexpr int C = W1 ? FFDIM : DM;
    __half* dst = W1 ? g_w1h : g_w2h;
    __shared__ float b[32][65];                 // b[c][r]
    int e = blockIdx.z;
    int c0 = blockIdx.x * 32, r0 = blockIdx.y * 64;
    const float* s = src + (size_t)e * R * C;
    __half* d = dst + (size_t)e * R * C;
    int lane = threadIdx.x & 31, w = threadIdx.x >> 5;
#pragma unroll
    for (int i = 0; i < 8; i++) {
        int r = w * 8 + i;
        b[lane][r] = s[(size_t)(r0 + r) * C + c0 + lane];
    }
    __syncthreads();
#pragma unroll
    for (int i = 0; i < 4; i++) {
        int c = w + 8 * i;
        __half2 h = __floats2half2_rn(b[c][2 * lane], b[c][2 * lane + 1]);
        *reinterpret_cast<__half2*>(d + (size_t)(c0 + c) * R + r0 + 2 * lane) = h;
    }
}

// ---------------- routing (parallel, order-preserving) ----------------
__global__ __launch_bounds__(256) void routeA_kernel() {
    __shared__ int wsum[8];
    int tid = threadIdx.x, lane = tid & 31, warp = tid >> 5;
    int t = blockIdx.x * 256 + tid;
    int i0 = g_topk_i[2 * t], i1 = g_topk_i[2 * t + 1];
    int lr0 = 0, lr1 = 0;
    for (int e = 0; e < NE; e++) {
        int v = (i0 == e || i1 == e) ? 1 : 0;
#pragma unroll
        for (int off = 1; off < 32; off <<= 1) {
            int u = __shfl_up_sync(0xffffffffu, v, off);
            if (lane >= off) v += u;
        }
        if (lane == 31) wsum[warp] = v;
        __syncthreads();
        int woff = 0, total = 0;
#pragma unroll
        for (int w = 0; w < 8; w++) { int s = wsum[w]; total += s; if (w < warp) woff += s; }
        int lr = woff + v;
        if (i0 == e) lr0 = lr;
        if (i1 == e) lr1 = lr;
        if (tid == 0) g_ccnt[blockIdx.x * NE + e] = total;
        __syncthreads();
    }
    g_lrank[2 * t] = lr0; g_lrank[2 * t + 1] = lr1;
}

__global__ __launch_bounds__(32) void routeB_kernel() {
    int e = threadIdx.x;
    if (e < NE) {
        int off = 0;
        for (int b = 0; b < NCHUNK; b++) {
            g_coff[b * NE + e] = off;
            off += g_ccnt[b * NE + e];
        }
        g_cnt[e] = min(off, CAP);
    }
}

__global__ __launch_bounds__(256) void routeC_kernel() {
    int tid = threadIdx.x;
    int t = blockIdx.x * 256 + tid;
#pragma unroll
    for (int j = 0; j < 2; j++) {
        int e = g_topk_i[2 * t + j];
        int rank = g_coff[blockIdx.x * NE + e] + g_lrank[2 * t + j];
        int s = (rank <= CAP) ? rank - 1 : -1;
        g_slot[2 * t + j] = s;
        if (s >= 0) g_idx[e * CAP + s] = t;
    }
}

// ---------------- expert GEMM: fp16 mma.sync m16n8k16 + ldmatrix + 3-stage cp.async ----------------
// SPLITK>1: blockIdx.z = e*SPLITK + half; each half covers KDIM/SPLITK, half1 -> g_oute2, no bias.
template<bool GATHER, bool RELU, int KDIM, int NDIM, int SPLITK>
__global__ __launch_bounds__(256, 2)
void gemm_kernel(const __half* __restrict__ Aglob,
                 const __half* __restrict__ Wglob,
                 const float* __restrict__ biasGlob) {
    extern __shared__ char smem[];
    __shared__ int sTok[BM];

    const int e = blockIdx.z / SPLITK;
    const int hlf = blockIdx.z % SPLITK;
    const int kOff = hlf * (KDIM / SPLITK);       // in halves
    const int rowBase = blockIdx.y * BM;
    const int nBase = blockIdx.x * BN;
    const int tid = threadIdx.x;

    const __half* Abase = GATHER ? Aglob : (g_h + (size_t)e * CAP * KDIM);
    const __half* W = Wglob + ((size_t)e * NDIM + nBase) * KDIM;
    const float* bias = biasGlob + e * NDIM;

    if (tid < BM) {
        int r = rowBase + tid;
        sTok[tid] = GATHER ? ((r < g_cnt[e]) ? g_idx[e * CAP + r] : -1) : (rowBase + tid);
    }
    __syncthreads();

    const unsigned smem_base = (unsigned)__cvta_generic_to_shared(smem);

    const int ldRow0 = tid >> 2;
    const int ldC0 = tid & 3;

    auto load_stage = [&](int slot, int kk) {    // kk in halves (absolute)
        unsigned aB = smem_base + slot * STAGE_BYTES;
        unsigned bB = aB + A_STAGE_BYTES;
#pragma unroll
        for (int i = 0; i < 2; i++) {
            int row = ldRow0 + i * 64;
            int r7 = row & 7;
            int tok = sTok[row];
            const __half* asrc = Abase + (size_t)((tok < 0) ? 0 : tok) * KDIM + kk;
            const __half* bsrc = W + (size_t)row * KDIM + kk;
#pragma unroll
            for (int j = 0; j < 2; j++) {
                int c = ldC0 + j * 4;
                unsigned sw = (unsigned)(row * 128 + ((c ^ r7) << 4));
                cp_async16(aB + sw, asrc + c * 8, (tok >= 0) ? 16 : 0);
                cp_async16(bB + sw, bsrc + c * 8, 16);
            }
        }
    };

    float acc[4][4][4];
#pragma unroll
    for (int mt = 0; mt < 4; mt++)
#pragma unroll
        for (int nt = 0; nt < 4; nt++)
#pragma unroll
            for (int i = 0; i < 4; i++) acc[mt][nt][i] = 0.f;

    const int warp = tid >> 5, lane = tid & 31;
    const int wm = warp >> 2, wn = warp & 3;
    const int t4 = lane >> 3;
    const int row7 = lane & 7;

    const int aRowByte = (wm * 64 + (t4 & 1) * 8 + row7) * 128;
    const int aG = (t4 >> 1);
    const int bRowByte = (wn * 32 + (t4 >> 1) * 8 + row7) * 128;
    const int bG = (t4 & 1);

    const int NIT = (KDIM / SPLITK) / BKH;

    load_stage(0, kOff); cp_commit();
    load_stage(1, kOff + BKH); cp_commit();

    int slot = 0, nslot = 2;
    for (int k = 0; k < NIT; k++) {
        cp_wait1();
        __syncthreads();

        int nk = k + 2;
        if (nk < NIT) load_stage(nslot, kOff + nk * BKH);
        cp_commit();

        const unsigned sA = smem_base + slot * STAGE_BYTES;
        const unsigned sB = sA + A_STAGE_BYTES;

#pragma unroll
        for (int gr = 0; gr < 4; gr++) {
            unsigned a[4][4], b[4][2];
#pragma unroll
            for (int mt = 0; mt < 4; mt++)
                ldsm_x4(a[mt], sA + aRowByte + mt * 2048 + ((((2 * gr) + aG) ^ row7) << 4));
#pragma unroll
            for (int ntp = 0; ntp < 2; ntp++) {
                unsigned r[4];
                ldsm_x4(r, sB + bRowByte + ntp * 2048 + ((((2 * gr) + bG) ^ row7) << 4));
                b[2 * ntp][0] = r[0]; b[2 * ntp][1] = r[1];
                b[2 * ntp + 1][0] = r[2]; b[2 * ntp + 1][1] = r[3];
            }
#pragma unroll
            for (int mt = 0; mt < 4; mt++)
#pragma unroll
                for (int nt = 0; nt < 4; nt++)
                    mma_f16(acc[mt][nt], a[mt], b[nt]);
        }
        slot = (slot == NSTG - 1) ? 0 : slot + 1;
        nslot = (nslot == NSTG - 1) ? 0 : nslot + 1;
    }

    // epilogue
    const int gid = lane >> 2, tig = lane & 3;
#pragma unroll
    for (int mt = 0; mt < 4; mt++) {
        int r0 = rowBase + wm * 64 + mt * 16 + gid;
#pragma unroll
        for (int nt = 0; nt < 4; nt++) {
            int c = nBase + wn * 32 + nt * 8 + 2 * tig;
            float bv0 = (hlf == 0) ? bias[c] : 0.f;
            float bv1 = (hlf == 0) ? bias[c + 1] : 0.f;
            float v00 = acc[mt][nt][0] + bv0;
            float v01 = acc[mt][nt][1] + bv1;
            float v10 = acc[mt][nt][2] + bv0;
            float v11 = acc[mt][nt][3] + bv1;
            if (RELU) {
                __half* OutH = g_h + (size_t)e * CAP * NDIM;
                *reinterpret_cast<__half2*>(OutH + (size_t)r0 * NDIM + c) =
                    __floats2half2_rn(fmaxf(v00, 0.f), fmaxf(v01, 0.f));
                *reinterpret_cast<__half2*>(OutH + (size_t)(r0 + 8) * NDIM + c) =
                    __floats2half2_rn(fmaxf(v10, 0.f), fmaxf(v11, 0.f));
            } else {
                float* OutF = ((hlf == 0) ? g_oute : g_oute2) + (size_t)e * CAP * NDIM;
                *reinterpret_cast<float2*>(OutF + (size_t)r0 * NDIM + c) = make_float2(v00, v01);
                *reinterpret_cast<float2*>(OutF + (size_t)(r0 + 8) * NDIM + c) = make_float2(v10, v11);
            }
        }
    }
}

// ---------------- combine (sums split-K halves) ----------------
__global__ __launch_bounds__(256) void combine_kernel(float* __restrict__ out) {
    int t = blockIdx.x;
    int i0 = g_topk_i[2 * t], i1 = g_topk_i[2 * t + 1];
    int s0 = g_slot[2 * t], s1 = g_slot[2 * t + 1];
    float w0 = g_topk_w[2 * t], w1v = g_topk_w[2 * t + 1];
    int d = threadIdx.x * 4;
    float4 a = make_float4(0.f, 0.f, 0.f, 0.f);
    if (s0 >= 0) {
        size_t off = ((size_t)i0 * CAP + s0) * DM + d;
        float4 v = *reinterpret_cast<const float4*>(g_oute + off);
        float4 u = *reinterpret_cast<const float4*>(g_oute2 + off);
        a.x += w0 * (v.x + u.x); a.y += w0 * (v.y + u.y);
        a.z += w0 * (v.z + u.z); a.w += w0 * (v.w + u.w);
    }
    if (s1 >= 0) {
        size_t off = ((size_t)i1 * CAP + s1) * DM + d;
        float4 v = *reinterpret_cast<const float4*>(g_oute + off);
        float4 u = *reinterpret_cast<const float4*>(g_oute2 + off);
        a.x += w1v * (v.x + u.x); a.y += w1v * (v.y + u.y);
        a.z += w1v * (v.z + u.z); a.w += w1v * (v.w + u.w);
    }
    *reinterpret_cast<float4*>(out + (size_t)t * DM + d) = a;
}

// ---------------- launch ----------------
extern "C" void kernel_launch(void* const* d_in, const int* in_sizes, int n_in,
                              void* d_out, int out_size) {
    (void)in_sizes; (void)n_in; (void)out_size;
    const float* x      = (const float*)d_in[0];
    const float* gate_w = (const float*)d_in[1];
    const float* gate_b = (const float*)d_in[2];
    const float* w1     = (const float*)d_in[3];
    const float* b1     = (const float*)d_in[4];
    const float* w2     = (const float*)d_in[5];
    const float* b2     = (const float*)d_in[6];
    float* out = (float*)d_out;

    static bool attr_done = false;
    if (!attr_done) {
        cudaFuncSetAttribute(gemm_kernel<true,  true,  DM,    FFDIM, 1>,
                             cudaFuncAttributeMaxDynamicSharedMemorySize, SMEM_BYTES);
        cudaFuncSetAttribute(gemm_kernel<false, false, FFDIM, DM,    2>,
                             cudaFuncAttributeMaxDynamicSharedMemorySize, SMEM_BYTES);
        attr_done = true;
    }

    static __half *p_xh = nullptr, *p_w1h = nullptr, *p_w2h = nullptr;
    if (!p_xh) {
        cudaGetSymbolAddress((void**)&p_xh,  g_xh);
        cudaGetSymbolAddress((void**)&p_w1h, g_w1h);
        cudaGetSymbolAddress((void**)&p_w2h, g_w2h);
    }

    gatex_kernel<<<S_TOK / 8, 256>>>(x, gate_w, gate_b);
    wtr_kernel<true ><<<dim3(FFDIM / 32, DM / 64, NE), 256>>>(w1);
    wtr_kernel<false><<<dim3(DM / 32, FFDIM / 64, NE), 256>>>(w2);

    routeA_kernel<<<NCHUNK, 256>>>();
    routeB_kernel<<<1, 32>>>();
    routeC_kernel<<<NCHUNK, 256>>>();

    gemm_kernel<true,  true,  DM,    FFDIM, 1>
        <<<dim3(FFDIM / BN, CAP / BM, NE), 256, SMEM_BYTES>>>(p_xh, p_w1h, b1);
    gemm_kernel<false, false, FFDIM, DM,    2>
        <<<dim3(DM / BN,    CAP / BM, NE * 2), 256, SMEM_BYTES>>>(nullptr, p_w2h, b2);
    combine_kernel<<<S_TOK, 256>>>(out);
}